// round 9
// baseline (speedup 1.0000x reference)
#include <cuda_runtime.h>
#include <cuda_fp16.h>
#include <cstdint>
#include <math.h>

#define BB 2
#define NN 1024
#define CIN 512
#define HH 16
#define DH 32
#define CZ 128

// ---------------- scratch (device globals; no allocation) ----------------
__device__ float g_mln[BB * NN * CIN];
__device__ float g_q[BB * NN * CIN];
__device__ float g_k[BB * NN * CIN];
__device__ float g_v[BB * NN * CIN];
__device__ float g_g[BB * NN * CIN];
__device__ float g_og[BB * NN * CIN];
__device__ float g_qk[(size_t)BB * HH * NN * NN];       // QK^T logits fp32 (128MB)
__device__ __half g_probs[(size_t)BB * HH * NN * NN];   // unnormalized exp fp16 (64MB)
__device__ float g_psum[BB * HH * NN];                  // softmax row sums

__device__ __forceinline__ void cp_async16(unsigned int saddr, const void* gptr) {
    asm volatile("cp.async.cg.shared.global [%0], [%1], 16;" :: "r"(saddr), "l"(gptr));
}
__device__ __forceinline__ void cp_commit() {
    asm volatile("cp.async.commit_group;" ::: "memory");
}
template <int N>
__device__ __forceinline__ void cp_wait() {
    asm volatile("cp.async.wait_group %0;" :: "n"(N) : "memory");
}

// ---------------- kernel 1a: LayerNorm(m) ----------------
__global__ __launch_bounds__(128) void ln_m_kernel(const float* __restrict__ m,
                                                   const float* __restrict__ w,
                                                   const float* __restrict__ b) {
    int row = blockIdx.x;
    int tid = threadIdx.x;
    const float4* mp = (const float4*)m + (size_t)row * 128;
    float4 x = mp[tid];
    float s = x.x + x.y + x.z + x.w;
    float q2 = x.x * x.x + x.y * x.y + x.z * x.z + x.w * x.w;
#pragma unroll
    for (int o = 16; o; o >>= 1) {
        s  += __shfl_xor_sync(0xffffffffu, s, o);
        q2 += __shfl_xor_sync(0xffffffffu, q2, o);
    }
    __shared__ float sS[4], sQ[4];
    __shared__ float s_mu, s_rstd;
    int wid = tid >> 5, lane = tid & 31;
    if (lane == 0) { sS[wid] = s; sQ[wid] = q2; }
    __syncthreads();
    if (tid == 0) {
        float ts = sS[0] + sS[1] + sS[2] + sS[3];
        float tq = sQ[0] + sQ[1] + sQ[2] + sQ[3];
        float mu = ts * (1.0f / 512.0f);
        float var = tq * (1.0f / 512.0f) - mu * mu;
        s_mu = mu;
        s_rstd = rsqrtf(var + 1e-5f);
    }
    __syncthreads();
    float mu = s_mu, rstd = s_rstd;
    float4 w4 = ((const float4*)w)[tid];
    float4 b4 = ((const float4*)b)[tid];
    float4 o;
    o.x = (x.x - mu) * rstd * w4.x + b4.x;
    o.y = (x.y - mu) * rstd * w4.y + b4.y;
    o.z = (x.z - mu) * rstd * w4.z + b4.z;
    o.w = (x.w - mu) * rstd * w4.w + b4.w;
    ((float4*)g_mln)[(size_t)row * 128 + tid] = o;
}

// ---------------- kernel 1b: projections q,k,v,g ----------------
__global__ __launch_bounds__(256) void proj_kernel(const float* __restrict__ wq,
                                                   const float* __restrict__ wk,
                                                   const float* __restrict__ wv,
                                                   const float* __restrict__ wg,
                                                   const float* __restrict__ bg) {
    __shared__ float As[16][68];
    __shared__ float Bs[16][68];
    int bx = blockIdx.x;
    int by = blockIdx.y;
    int tid = threadIdx.x;
    int tx = tid & 15, ty = tid >> 4;
    int sel = bx >> 3;
    int cl0 = (bx & 7) * 64;
    const float* W = (sel == 0) ? wq : (sel == 1) ? wk : (sel == 2) ? wv : wg;
    float acc[4][4] = {};
    int aRow = tid >> 2, aK4 = (tid & 3) * 4;
    int bK = tid >> 4, bC4 = (tid & 15) * 4;
    for (int k0 = 0; k0 < 512; k0 += 16) {
        float4 va = *(const float4*)(g_mln + (size_t)(by * 64 + aRow) * 512 + k0 + aK4);
        float4 vb = *(const float4*)(W + (size_t)(k0 + bK) * 512 + cl0 + bC4);
        __syncthreads();
        As[aK4 + 0][aRow] = va.x;
        As[aK4 + 1][aRow] = va.y;
        As[aK4 + 2][aRow] = va.z;
        As[aK4 + 3][aRow] = va.w;
        *(float4*)&Bs[bK][bC4] = vb;
        __syncthreads();
#pragma unroll
        for (int kk = 0; kk < 16; ++kk) {
            float4 a = *(const float4*)&As[kk][ty * 4];
            float4 b = *(const float4*)&Bs[kk][tx * 4];
            float ar[4] = {a.x, a.y, a.z, a.w};
            float br[4] = {b.x, b.y, b.z, b.w};
#pragma unroll
            for (int i = 0; i < 4; ++i)
#pragma unroll
                for (int j = 0; j < 4; ++j) acc[i][j] += ar[i] * br[j];
        }
    }
    const float qscale = 0.17677669529663687f;
#pragma unroll
    for (int i = 0; i < 4; ++i) {
        int row = by * 64 + ty * 4 + i;
#pragma unroll
        for (int j = 0; j < 4; ++j) {
            int col = cl0 + tx * 4 + j;
            size_t oidx = (size_t)row * 512 + col;
            float v = acc[i][j];
            if (sel == 0)      g_q[oidx] = v * qscale;
            else if (sel == 1) g_k[oidx] = v;
            else if (sel == 2) g_v[oidx] = v;
            else               g_g[oidx] = 1.0f / (1.0f + __expf(-(v + bg[col])));
        }
    }
}

// ---------------- kernel 1c: qk[b,h,q,k] = q . k  (batched GEMM) ----------------
__global__ __launch_bounds__(512) void qk_kernel() {
    __shared__ float Qs[128][36];
    __shared__ float Ks[128][36];
    int tid = threadIdx.x;
    int bh = blockIdx.y;
    int b = bh >> 4, h = bh & 15;
    int q0 = (blockIdx.x >> 3) * 128;
    int k0 = (blockIdx.x & 7) * 128;
    const float* qb = g_q + (size_t)(b * 1024) * 512 + h * 32;
    const float* kb = g_k + (size_t)(b * 1024) * 512 + h * 32;
#pragma unroll
    for (int u = 0; u < 2; ++u) {
        int fid = tid + 512 * u;
        int row = fid >> 3, d4 = (fid & 7) * 4;
        *(float4*)&Qs[row][d4] = *(const float4*)(qb + (size_t)(q0 + row) * 512 + d4);
        *(float4*)&Ks[row][d4] = *(const float4*)(kb + (size_t)(k0 + row) * 512 + d4);
    }
    __syncthreads();
    int tx = tid & 15, ty = tid >> 4;
    float acc[4][8] = {};
#pragma unroll
    for (int d4 = 0; d4 < 8; ++d4) {
        float4 av[4], bv[8];
#pragma unroll
        for (int i = 0; i < 4; ++i) av[i] = *(const float4*)&Qs[ty + 32 * i][d4 * 4];
#pragma unroll
        for (int j = 0; j < 8; ++j) bv[j] = *(const float4*)&Ks[tx + 16 * j][d4 * 4];
#pragma unroll
        for (int i = 0; i < 4; ++i)
#pragma unroll
            for (int j = 0; j < 8; ++j)
                acc[i][j] += av[i].x * bv[j].x + av[i].y * bv[j].y +
                             av[i].z * bv[j].z + av[i].w * bv[j].w;
    }
    float* ob = g_qk + ((size_t)bh * 1024 + q0) * 1024 + k0;
#pragma unroll
    for (int i = 0; i < 4; ++i)
#pragma unroll
        for (int j = 0; j < 8; ++j)
            ob[(size_t)(ty + 32 * i) * 1024 + tx + 16 * j] = acc[i][j];
}

// ---------------- kernel 2: fused pair-bias + (+qk) + softmax -> fp16 probs ----------------
// dyn smem floats: S[16384] | Zs0[128*132] | Zs1[128*132] | wzw2[1024 (half2)] | s1[16] | c0[16]
#define ZROW 132
#define ZTILE (128 * ZROW)
__global__ __launch_bounds__(512) void bias_attn_kernel(const float* __restrict__ z,
                                                        const float* __restrict__ mask,
                                                        const float* __restrict__ lzw,
                                                        const float* __restrict__ lzb,
                                                        const float* __restrict__ wz) {
    extern __shared__ float smbuf[];
    float* S = smbuf;                                     // 16 x 1024
    float* Zbuf[2] = { smbuf + 16384, smbuf + 16384 + ZTILE };
    __half2* wzw2 = (__half2*)(smbuf + 16384 + 2 * ZTILE);   // [c2][h]
    float* s1 = smbuf + 16384 + 2 * ZTILE + 1024;
    float* c0 = s1 + 16;

    int tid = threadIdx.x;
    int bq = blockIdx.x;
    int b = bq >> 10, q = bq & 1023;

    // prologue: pack c-pair weights wzw2[c2*16+h] = (lzw*wz)[2c2][h], (lzw*wz)[2c2+1][h]
    for (int idx = tid; idx < 1024; idx += 512) {
        int c2 = idx >> 4, h = idx & 15;
        wzw2[idx] = __floats2half2_rn(lzw[2 * c2] * wz[(2 * c2) * 16 + h],
                                      lzw[2 * c2 + 1] * wz[(2 * c2 + 1) * 16 + h]);
    }
    if (tid < 16) {
        float a = 0.f, bb2 = 0.f;
#pragma unroll 4
        for (int c = 0; c < 128; ++c) {
            a   += lzw[c] * wz[c * 16 + tid];
            bb2 += lzb[c] * wz[c * 16 + tid];
        }
        s1[tid] = a;
        c0[tid] = bb2;
    }

    // tile 0 loads (coalesced cp.async)
    const float* zrow = z + (size_t)bq * 1024 * 128;   // this (b,q)'s z[k][c] slab
    unsigned int zs_base[2];
    zs_base[0] = (unsigned int)__cvta_generic_to_shared(Zbuf[0]);
    zs_base[1] = (unsigned int)__cvta_generic_to_shared(Zbuf[1]);
#pragma unroll
    for (int i = 0; i < 8; ++i) {
        int cid = tid + i * 512;
        int row = cid >> 5, ch = cid & 31;
        cp_async16(zs_base[0] + (row * ZROW + ch * 4) * 4, zrow + row * 128 + ch * 4);
    }
    cp_commit();

    int r = tid >> 2;          // row within tile
    int qd = tid & 3;          // c-quarter
    int h0 = qd * 4;           // heads this lane writes
    float s1r[4], c0r[4];
#pragma unroll
    for (int j = 0; j < 4; ++j) { s1r[j] = 0.f; c0r[j] = 0.f; }   // filled after first sync

    float dacc[16];
    const __half2 hz = __float2half2_rn(0.f);

    bool s1_loaded = false;

    for (int t = 0; t < 8; ++t) {
        __syncthreads();    // prev compute done before overwriting its buffer
        if (t < 7) {
            const float* src = zrow + (t + 1) * 128 * 128;
            unsigned int dstb = zs_base[(t + 1) & 1];
#pragma unroll
            for (int i = 0; i < 8; ++i) {
                int cid = tid + i * 512;
                int row = cid >> 5, ch = cid & 31;
                cp_async16(dstb + (row * ZROW + ch * 4) * 4, src + row * 128 + ch * 4);
            }
            cp_commit();
            cp_wait<1>();
        } else {
            cp_wait<0>();
        }
        __syncthreads();    // tile t visible to all; prologue smem also ready (t==0)

        if (!s1_loaded) {
#pragma unroll
            for (int j = 0; j < 4; ++j) { s1r[j] = s1[h0 + j]; c0r[j] = c0[h0 + j]; }
            s1_loaded = true;
        }

        const float* Zt = Zbuf[t & 1] + r * ZROW + qd * 32;
        float sm = 0.f, sq = 0.f;
#pragma unroll
        for (int hh = 0; hh < 16; ++hh) dacc[hh] = 0.f;
        __half2 acc[16];
#pragma unroll
        for (int hh = 0; hh < 16; ++hh) acc[hh] = hz;

#pragma unroll
        for (int j = 0; j < 8; ++j) {
            float4 x = *(const float4*)(Zt + j * 4);
            sm += (x.x + x.y) + (x.z + x.w);
            sq += x.x * x.x; sq += x.y * x.y; sq += x.z * x.z; sq += x.w * x.w;
            __half2 xa = __floats2half2_rn(x.x, x.y);
            __half2 xb = __floats2half2_rn(x.z, x.w);
            const float4* wv = (const float4*)(wzw2 + (size_t)(qd * 16 + j * 2) * 16);
            float4 wreg[8];
#pragma unroll
            for (int u = 0; u < 8; ++u) wreg[u] = wv[u];
            const __half2* wa = (const __half2*)&wreg[0];   // 16 half2 for even/odd pair a
            const __half2* wb = (const __half2*)&wreg[4];   // 16 half2 for pair b
#pragma unroll
            for (int hh = 0; hh < 16; ++hh) acc[hh] = __hfma2(xa, wa[hh], acc[hh]);
#pragma unroll
            for (int hh = 0; hh < 16; ++hh) acc[hh] = __hfma2(xb, wb[hh], acc[hh]);
            if (j == 3 || j == 7) {
#pragma unroll
                for (int hh = 0; hh < 16; ++hh) {
                    float2 f = __half22float2(acc[hh]);
                    dacc[hh] += f.x + f.y;
                    acc[hh] = hz;
                }
            }
        }

        // butterfly over the 4 lanes of this row
#pragma unroll
        for (int hh = 0; hh < 16; ++hh) {
            dacc[hh] += __shfl_xor_sync(0xffffffffu, dacc[hh], 1);
            dacc[hh] += __shfl_xor_sync(0xffffffffu, dacc[hh], 2);
        }
        sm += __shfl_xor_sync(0xffffffffu, sm, 1);
        sm += __shfl_xor_sync(0xffffffffu, sm, 2);
        sq += __shfl_xor_sync(0xffffffffu, sq, 1);
        sq += __shfl_xor_sync(0xffffffffu, sq, 2);

        int k = t * 128 + r;
        float mu = sm * (1.0f / 128.0f);
        float rstd = rsqrtf(sq * (1.0f / 128.0f) - mu * mu + 1e-5f);
        float mb = 1e9f * (mask[b * 1024 + k] - 1.0f);
#pragma unroll
        for (int j = 0; j < 4; ++j)
            S[(h0 + j) * 1024 + k] = rstd * (dacc[h0 + j] - mu * s1r[j]) + c0r[j] + mb;
    }
    __syncthreads();

    // ---- phase B: warp w owns head w: add qk logits, softmax, fp16 probs ----
    {
        int h = tid >> 5, lane = tid & 31;
        const float4* qkr = (const float4*)(g_qk + (((size_t)(b * 16 + h)) * 1024 + q) * 1024);
        float4 sv[8];
        float mx = -1e30f;
#pragma unroll
        for (int i = 0; i < 8; ++i) {
            float4 s = *(const float4*)&S[h * 1024 + lane * 4 + i * 128];
            float4 qk = qkr[lane + i * 32];
            s.x += qk.x; s.y += qk.y; s.z += qk.z; s.w += qk.w;
            sv[i] = s;
            mx = fmaxf(mx, fmaxf(fmaxf(s.x, s.y), fmaxf(s.z, s.w)));
        }
#pragma unroll
        for (int o = 16; o; o >>= 1) mx = fmaxf(mx, __shfl_xor_sync(0xffffffffu, mx, o));

        __half* prow = g_probs + (((size_t)(b * 16 + h)) * 1024 + q) * 1024;
        float sum = 0.f;
#pragma unroll
        for (int i = 0; i < 8; ++i) {
            float e0 = __expf(sv[i].x - mx);
            float e1 = __expf(sv[i].y - mx);
            float e2 = __expf(sv[i].z - mx);
            float e3 = __expf(sv[i].w - mx);
            sum += (e0 + e1) + (e2 + e3);
            __half2 p0 = __floats2half2_rn(e0, e1);
            __half2 p1 = __floats2half2_rn(e2, e3);
            uint2 pk;
            pk.x = reinterpret_cast<unsigned int&>(p0);
            pk.y = reinterpret_cast<unsigned int&>(p1);
            *(uint2*)(prow + lane * 4 + i * 128) = pk;
        }
#pragma unroll
        for (int o = 16; o; o >>= 1) sum += __shfl_xor_sync(0xffffffffu, sum, o);
        if (lane == 0) g_psum[(b * 16 + h) * 1024 + q] = sum;
    }
}

// ---------------- kernel 3: AV + gate ----------------
__global__ __launch_bounds__(256) void av_kernel() {
    __shared__ __half Ps[128][72];
    __shared__ float  Vs[64][36];
    int tid = threadIdx.x;
    int tx = tid & 7;
    int ty = tid >> 3;
    int bh = blockIdx.y;
    int b = bh >> 4, h = bh & 15;
    int q0 = blockIdx.x * 128;

    const __half* pb = g_probs + ((size_t)bh * 1024 + q0) * 1024;
    const float* vb = g_v + (size_t)b * 1024 * 512 + h * 32;

    float acc[4][4] = {};

    for (int kt = 0; kt < 16; ++kt) {
        __syncthreads();
#pragma unroll
        for (int u = 0; u < 4; ++u) {
            int id = tid + 256 * u;
            int row = id >> 3, c8 = id & 7;
            *(uint4*)&Ps[row][c8 * 8] = *(const uint4*)(pb + (size_t)row * 1024 + kt * 64 + c8 * 8);
        }
#pragma unroll
        for (int u = 0; u < 2; ++u) {
            int id = tid + 256 * u;
            int row = id >> 3, d4 = id & 7;
            *(float4*)&Vs[row][d4 * 4] = *(const float4*)(vb + (size_t)(kt * 64 + row) * 512 + d4 * 4);
        }
        __syncthreads();
#pragma unroll 4
        for (int k2 = 0; k2 < 32; ++k2) {
            int kk = k2 * 2;
            float4 v0 = *(const float4*)&Vs[kk][tx * 4];
            float4 v1 = *(const float4*)&Vs[kk + 1][tx * 4];
#pragma unroll
            for (int i = 0; i < 4; ++i) {
                float2 pf = __half22float2(*(const __half2*)&Ps[ty * 4 + i][kk]);
                acc[i][0] += pf.x * v0.x + pf.y * v1.x;
                acc[i][1] += pf.x * v0.y + pf.y * v1.y;
                acc[i][2] += pf.x * v0.z + pf.y * v1.z;
                acc[i][3] += pf.x * v0.w + pf.y * v1.w;
            }
        }
    }

#pragma unroll
    for (int i = 0; i < 4; ++i) {
        int q = q0 + ty * 4 + i;
        float inv = 1.0f / g_psum[bh * 1024 + q];
        size_t gi = ((size_t)(b * 1024 + q)) * 512 + h * 32 + tx * 4;
        float4 gv = *(const float4*)&g_g[gi];
        float4 o;
        o.x = acc[i][0] * inv * gv.x;
        o.y = acc[i][1] * inv * gv.y;
        o.z = acc[i][2] * inv * gv.z;
        o.w = acc[i][3] * inv * gv.w;
        *(float4*)&g_og[gi] = o;
    }
}

// ---------------- kernel 4: out = og @ w_o + b_o ----------------
__global__ __launch_bounds__(256) void out_kernel(const float* __restrict__ wo,
                                                  const float* __restrict__ bo,
                                                  float* __restrict__ out) {
    __shared__ float As[16][68];
    __shared__ float Bs[16][68];
    int bx = blockIdx.x;
    int by = blockIdx.y;
    int tid = threadIdx.x;
    int tx = tid & 15, ty = tid >> 4;
    int cl0 = bx * 64;
    float acc[4][4] = {};
    int aRow = tid >> 2, aK4 = (tid & 3) * 4;
    int bK = tid >> 4, bC4 = (tid & 15) * 4;
    for (int k0 = 0; k0 < 512; k0 += 16) {
        float4 va = *(const float4*)(g_og + (size_t)(by * 64 + aRow) * 512 + k0 + aK4);
        float4 vb = *(const float4*)(wo + (size_t)(k0 + bK) * 512 + cl0 + bC4);
        __syncthreads();
        As[aK4 + 0][aRow] = va.x;
        As[aK4 + 1][aRow] = va.y;
        As[aK4 + 2][aRow] = va.z;
        As[aK4 + 3][aRow] = va.w;
        *(float4*)&Bs[bK][bC4] = vb;
        __syncthreads();
#pragma unroll
        for (int kk = 0; kk < 16; ++kk) {
            float4 a = *(const float4*)&As[kk][ty * 4];
            float4 b = *(const float4*)&Bs[kk][tx * 4];
            float ar[4] = {a.x, a.y, a.z, a.w};
            float br[4] = {b.x, b.y, b.z, b.w};
#pragma unroll
            for (int i = 0; i < 4; ++i)
#pragma unroll
                for (int j = 0; j < 4; ++j) acc[i][j] += ar[i] * br[j];
        }
    }
#pragma unroll
    for (int i = 0; i < 4; ++i) {
        int row = by * 64 + ty * 4 + i;
#pragma unroll
        for (int j = 0; j < 4; ++j) {
            int col = cl0 + tx * 4 + j;
            out[(size_t)row * 512 + col] = acc[i][j] + bo[col];
        }
    }
}

// ---------------- launch ----------------
extern "C" void kernel_launch(void* const* d_in, const int* in_sizes, int n_in,
                              void* d_out, int out_size) {
    const float* m      = (const float*)d_in[0];
    const float* z      = (const float*)d_in[1];
    const float* mask   = (const float*)d_in[2];
    const float* ln_m_w = (const float*)d_in[3];
    const float* ln_m_b = (const float*)d_in[4];
    const float* ln_z_w = (const float*)d_in[5];
    const float* ln_z_b = (const float*)d_in[6];
    const float* w_z    = (const float*)d_in[7];
    const float* w_q    = (const float*)d_in[8];
    const float* w_k    = (const float*)d_in[9];
    const float* w_v    = (const float*)d_in[10];
    const float* w_g    = (const float*)d_in[11];
    const float* b_g    = (const float*)d_in[12];
    const float* w_o    = (const float*)d_in[13];
    const float* b_o    = (const float*)d_in[14];
    float* out = (float*)d_out;

    const int smem_bias = (16384 + 2 * ZTILE + 1024 + 32) * 4;   // 204,928 B
    cudaFuncSetAttribute(bias_attn_kernel,
                         cudaFuncAttributeMaxDynamicSharedMemorySize, smem_bias);

    ln_m_kernel<<<BB * NN, 128>>>(m, ln_m_w, ln_m_b);
    proj_kernel<<<dim3(32, 32), 256>>>(w_q, w_k, w_v, w_g, b_g);
    qk_kernel<<<dim3(64, 32), 512>>>();
    bias_attn_kernel<<<BB * NN, 512, smem_bias>>>(z, mask, ln_z_w, ln_z_b, w_z);
    av_kernel<<<dim3(8, 32), 256>>>();
    out_kernel<<<dim3(8, 32), 256>>>(w_o, b_o, out);
}

// round 10
// speedup vs baseline: 1.6883x; 1.6883x over previous
#include <cuda_runtime.h>
#include <cuda_fp16.h>
#include <cstdint>
#include <math.h>

#define BB 2
#define NN 1024
#define CIN 512
#define HH 16
#define DH 32
#define CZ 128

// ---------------- scratch (device globals; no allocation) ----------------
__device__ float g_mln[BB * NN * CIN];
__device__ float g_q[BB * NN * CIN];
__device__ float g_k[BB * NN * CIN];
__device__ float g_v[BB * NN * CIN];
__device__ float g_g[BB * NN * CIN];
__device__ float g_og[BB * NN * CIN];
__device__ float g_qk[(size_t)BB * HH * NN * NN];       // QK^T logits fp32 (128MB)
__device__ __half g_probs[(size_t)BB * HH * NN * NN];   // unnormalized exp fp16 (64MB)
__device__ float g_psum[BB * HH * NN];                  // softmax row sums

__device__ __forceinline__ void cp_async16(unsigned int saddr, const void* gptr) {
    asm volatile("cp.async.cg.shared.global [%0], [%1], 16;" :: "r"(saddr), "l"(gptr));
}
__device__ __forceinline__ void cp_commit() {
    asm volatile("cp.async.commit_group;" ::: "memory");
}
template <int N>
__device__ __forceinline__ void cp_wait() {
    asm volatile("cp.async.wait_group %0;" :: "n"(N) : "memory");
}

// ---------------- kernel 1a: LayerNorm(m) ----------------
__global__ __launch_bounds__(128) void ln_m_kernel(const float* __restrict__ m,
                                                   const float* __restrict__ w,
                                                   const float* __restrict__ b) {
    int row = blockIdx.x;
    int tid = threadIdx.x;
    const float4* mp = (const float4*)m + (size_t)row * 128;
    float4 x = mp[tid];
    float s = x.x + x.y + x.z + x.w;
    float q2 = x.x * x.x + x.y * x.y + x.z * x.z + x.w * x.w;
#pragma unroll
    for (int o = 16; o; o >>= 1) {
        s  += __shfl_xor_sync(0xffffffffu, s, o);
        q2 += __shfl_xor_sync(0xffffffffu, q2, o);
    }
    __shared__ float sS[4], sQ[4];
    __shared__ float s_mu, s_rstd;
    int wid = tid >> 5, lane = tid & 31;
    if (lane == 0) { sS[wid] = s; sQ[wid] = q2; }
    __syncthreads();
    if (tid == 0) {
        float ts = sS[0] + sS[1] + sS[2] + sS[3];
        float tq = sQ[0] + sQ[1] + sQ[2] + sQ[3];
        float mu = ts * (1.0f / 512.0f);
        float var = tq * (1.0f / 512.0f) - mu * mu;
        s_mu = mu;
        s_rstd = rsqrtf(var + 1e-5f);
    }
    __syncthreads();
    float mu = s_mu, rstd = s_rstd;
    float4 w4 = ((const float4*)w)[tid];
    float4 b4 = ((const float4*)b)[tid];
    float4 o;
    o.x = (x.x - mu) * rstd * w4.x + b4.x;
    o.y = (x.y - mu) * rstd * w4.y + b4.y;
    o.z = (x.z - mu) * rstd * w4.z + b4.z;
    o.w = (x.w - mu) * rstd * w4.w + b4.w;
    ((float4*)g_mln)[(size_t)row * 128 + tid] = o;
}

// ---------------- kernel 1b: projections q,k,v,g ----------------
__global__ __launch_bounds__(256) void proj_kernel(const float* __restrict__ wq,
                                                   const float* __restrict__ wk,
                                                   const float* __restrict__ wv,
                                                   const float* __restrict__ wg,
                                                   const float* __restrict__ bg) {
    __shared__ float As[16][68];
    __shared__ float Bs[16][68];
    int bx = blockIdx.x;
    int by = blockIdx.y;
    int tid = threadIdx.x;
    int tx = tid & 15, ty = tid >> 4;
    int sel = bx >> 3;
    int cl0 = (bx & 7) * 64;
    const float* W = (sel == 0) ? wq : (sel == 1) ? wk : (sel == 2) ? wv : wg;
    float acc[4][4] = {};
    int aRow = tid >> 2, aK4 = (tid & 3) * 4;
    int bK = tid >> 4, bC4 = (tid & 15) * 4;
    for (int k0 = 0; k0 < 512; k0 += 16) {
        float4 va = *(const float4*)(g_mln + (size_t)(by * 64 + aRow) * 512 + k0 + aK4);
        float4 vb = *(const float4*)(W + (size_t)(k0 + bK) * 512 + cl0 + bC4);
        __syncthreads();
        As[aK4 + 0][aRow] = va.x;
        As[aK4 + 1][aRow] = va.y;
        As[aK4 + 2][aRow] = va.z;
        As[aK4 + 3][aRow] = va.w;
        *(float4*)&Bs[bK][bC4] = vb;
        __syncthreads();
#pragma unroll
        for (int kk = 0; kk < 16; ++kk) {
            float4 a = *(const float4*)&As[kk][ty * 4];
            float4 b = *(const float4*)&Bs[kk][tx * 4];
            float ar[4] = {a.x, a.y, a.z, a.w};
            float br[4] = {b.x, b.y, b.z, b.w};
#pragma unroll
            for (int i = 0; i < 4; ++i)
#pragma unroll
                for (int j = 0; j < 4; ++j) acc[i][j] += ar[i] * br[j];
        }
    }
    const float qscale = 0.17677669529663687f;
#pragma unroll
    for (int i = 0; i < 4; ++i) {
        int row = by * 64 + ty * 4 + i;
#pragma unroll
        for (int j = 0; j < 4; ++j) {
            int col = cl0 + tx * 4 + j;
            size_t oidx = (size_t)row * 512 + col;
            float v = acc[i][j];
            if (sel == 0)      g_q[oidx] = v * qscale;
            else if (sel == 1) g_k[oidx] = v;
            else if (sel == 2) g_v[oidx] = v;
            else               g_g[oidx] = 1.0f / (1.0f + __expf(-(v + bg[col])));
        }
    }
}

// ---------------- kernel 1c: qk[b,h,q,k] = q . k  (batched GEMM) ----------------
__global__ __launch_bounds__(512) void qk_kernel() {
    __shared__ float Qs[128][36];
    __shared__ float Ks[128][36];
    int tid = threadIdx.x;
    int bh = blockIdx.y;
    int b = bh >> 4, h = bh & 15;
    int q0 = (blockIdx.x >> 3) * 128;
    int k0 = (blockIdx.x & 7) * 128;
    const float* qb = g_q + (size_t)(b * 1024) * 512 + h * 32;
    const float* kb = g_k + (size_t)(b * 1024) * 512 + h * 32;
#pragma unroll
    for (int u = 0; u < 2; ++u) {
        int fid = tid + 512 * u;
        int row = fid >> 3, d4 = (fid & 7) * 4;
        *(float4*)&Qs[row][d4] = *(const float4*)(qb + (size_t)(q0 + row) * 512 + d4);
        *(float4*)&Ks[row][d4] = *(const float4*)(kb + (size_t)(k0 + row) * 512 + d4);
    }
    __syncthreads();
    int tx = tid & 15, ty = tid >> 4;
    float acc[4][8] = {};
#pragma unroll
    for (int d4 = 0; d4 < 8; ++d4) {
        float4 av[4], bv[8];
#pragma unroll
        for (int i = 0; i < 4; ++i) av[i] = *(const float4*)&Qs[ty + 32 * i][d4 * 4];
#pragma unroll
        for (int j = 0; j < 8; ++j) bv[j] = *(const float4*)&Ks[tx + 16 * j][d4 * 4];
#pragma unroll
        for (int i = 0; i < 4; ++i)
#pragma unroll
            for (int j = 0; j < 8; ++j)
                acc[i][j] += av[i].x * bv[j].x + av[i].y * bv[j].y +
                             av[i].z * bv[j].z + av[i].w * bv[j].w;
    }
    float* ob = g_qk + ((size_t)bh * 1024 + q0) * 1024 + k0;
#pragma unroll
    for (int i = 0; i < 4; ++i)
#pragma unroll
        for (int j = 0; j < 8; ++j)
            ob[(size_t)(ty + 32 * i) * 1024 + tx + 16 * j] = acc[i][j];
}

// ---------------- kernel 2: fused pair-bias + (+qk) + softmax -> fp16 probs ----------------
// dyn smem floats: S[16384] | Zs0[128*132] | Zs1[128*132] | wzw2[1024 half2] | s1[16] | c0[16]
#define ZROW 132
#define ZTILE (128 * ZROW)
__global__ __launch_bounds__(512, 1) void bias_attn_kernel(const float* __restrict__ z,
                                                           const float* __restrict__ mask,
                                                           const float* __restrict__ lzw,
                                                           const float* __restrict__ lzb,
                                                           const float* __restrict__ wz) {
    extern __shared__ float smbuf[];
    float* S = smbuf;                                     // 16 x 1024
    float* Zb0 = smbuf + 16384;
    float* Zb1 = smbuf + 16384 + ZTILE;
    __half2* wzw2 = (__half2*)(smbuf + 16384 + 2 * ZTILE);   // [c2][h]
    float* s1 = smbuf + 16384 + 2 * ZTILE + 1024;
    float* c0 = s1 + 16;

    int tid = threadIdx.x;
    int bq = blockIdx.x;
    int b = bq >> 10, q = bq & 1023;

    // prologue: pack c-pair weights wzw2[c2*16+h] = ((lzw*wz)[2c2][h], (lzw*wz)[2c2+1][h])
    for (int idx = tid; idx < 1024; idx += 512) {
        int c2 = idx >> 4, h = idx & 15;
        wzw2[idx] = __floats2half2_rn(lzw[2 * c2] * wz[(2 * c2) * 16 + h],
                                      lzw[2 * c2 + 1] * wz[(2 * c2 + 1) * 16 + h]);
    }
    if (tid < 16) {
        float a = 0.f, bb2 = 0.f;
#pragma unroll 4
        for (int c = 0; c < 128; ++c) {
            a   += lzw[c] * wz[c * 16 + tid];
            bb2 += lzb[c] * wz[c * 16 + tid];
        }
        s1[tid] = a;
        c0[tid] = bb2;
    }

    // tile 0 loads (coalesced cp.async)
    const float* zrow = z + (size_t)bq * 1024 * 128;   // this (b,q)'s z[k][c] slab
    unsigned int zs0 = (unsigned int)__cvta_generic_to_shared(Zb0);
    unsigned int zs1 = (unsigned int)__cvta_generic_to_shared(Zb1);
#pragma unroll
    for (int i = 0; i < 8; ++i) {
        int cid = tid + i * 512;
        int row = cid >> 5, ch = cid & 31;
        cp_async16(zs0 + (row * ZROW + ch * 4) * 4, zrow + row * 128 + ch * 4);
    }
    cp_commit();

    int r = tid >> 2;          // row within tile
    int qd = tid & 3;          // c-quarter
    int h0 = qd * 4;           // heads this lane writes
    float s1r0 = 0.f, s1r1 = 0.f, s1r2 = 0.f, s1r3 = 0.f;
    float c0r0 = 0.f, c0r1 = 0.f, c0r2 = 0.f, c0r3 = 0.f;

    const __half2 hz = __float2half2_rn(0.f);
    bool s1_loaded = false;

    for (int t = 0; t < 8; ++t) {
        __syncthreads();    // prev compute done before overwriting its buffer
        if (t < 7) {
            const float* src = zrow + (t + 1) * 128 * 128;
            unsigned int dstb = ((t + 1) & 1) ? zs1 : zs0;
#pragma unroll
            for (int i = 0; i < 8; ++i) {
                int cid = tid + i * 512;
                int row = cid >> 5, ch = cid & 31;
                cp_async16(dstb + (row * ZROW + ch * 4) * 4, src + row * 128 + ch * 4);
            }
            cp_commit();
            cp_wait<1>();
        } else {
            cp_wait<0>();
        }
        __syncthreads();    // tile t visible to all; prologue smem also ready (t==0)

        if (!s1_loaded) {
            s1r0 = s1[h0 + 0]; s1r1 = s1[h0 + 1]; s1r2 = s1[h0 + 2]; s1r3 = s1[h0 + 3];
            c0r0 = c0[h0 + 0]; c0r1 = c0[h0 + 1]; c0r2 = c0[h0 + 2]; c0r3 = c0[h0 + 3];
            s1_loaded = true;
        }

        const float* Zt = ((t & 1) ? Zb1 : Zb0) + r * ZROW + qd * 32;
        float sm = 0.f, sq = 0.f;
        __half2 acc[16];
#pragma unroll
        for (int hh = 0; hh < 16; ++hh) acc[hh] = hz;

#pragma unroll
        for (int j = 0; j < 8; ++j) {
            float4 x = *(const float4*)(Zt + j * 4);
            sm += (x.x + x.y) + (x.z + x.w);
            sq += x.x * x.x; sq += x.y * x.y; sq += x.z * x.z; sq += x.w * x.w;
            __half2 xa = __floats2half2_rn(x.x, x.y);
            __half2 xb = __floats2half2_rn(x.z, x.w);
            const float4* wv = (const float4*)(wzw2 + (size_t)(qd * 16 + j * 2) * 16);
            {
                float4 wra[4] = { wv[0], wv[1], wv[2], wv[3] };
                const __half2* wa = (const __half2*)wra;
#pragma unroll
                for (int hh = 0; hh < 16; ++hh) acc[hh] = __hfma2(xa, wa[hh], acc[hh]);
            }
            {
                float4 wrb[4] = { wv[4], wv[5], wv[6], wv[7] };
                const __half2* wb = (const __half2*)wrb;
#pragma unroll
                for (int hh = 0; hh < 16; ++hh) acc[hh] = __hfma2(xb, wb[hh], acc[hh]);
            }
        }

        // fold fp16 pairs -> fp32, then butterfly over the 4 lanes of this row
        float dred[16];
#pragma unroll
        for (int hh = 0; hh < 16; ++hh) {
            float2 f = __half22float2(acc[hh]);
            dred[hh] = f.x + f.y;
        }
#pragma unroll
        for (int hh = 0; hh < 16; ++hh) {
            dred[hh] += __shfl_xor_sync(0xffffffffu, dred[hh], 1);
            dred[hh] += __shfl_xor_sync(0xffffffffu, dred[hh], 2);
        }
        sm += __shfl_xor_sync(0xffffffffu, sm, 1);
        sm += __shfl_xor_sync(0xffffffffu, sm, 2);
        sq += __shfl_xor_sync(0xffffffffu, sq, 1);
        sq += __shfl_xor_sync(0xffffffffu, sq, 2);

        int k = t * 128 + r;
        float mu = sm * (1.0f / 128.0f);
        float rstd = rsqrtf(sq * (1.0f / 128.0f) - mu * mu + 1e-5f);
        float mb = 1e9f * (mask[b * 1024 + k] - 1.0f);
        S[(h0 + 0) * 1024 + k] = rstd * (dred[h0 + 0] - mu * s1r0) + c0r0 + mb;
        S[(h0 + 1) * 1024 + k] = rstd * (dred[h0 + 1] - mu * s1r1) + c0r1 + mb;
        S[(h0 + 2) * 1024 + k] = rstd * (dred[h0 + 2] - mu * s1r2) + c0r2 + mb;
        S[(h0 + 3) * 1024 + k] = rstd * (dred[h0 + 3] - mu * s1r3) + c0r3 + mb;
    }
    __syncthreads();

    // ---- phase B: warp w owns head w: add qk logits, softmax, fp16 probs ----
    {
        int h = tid >> 5, lane = tid & 31;
        const float4* qkr = (const float4*)(g_qk + (((size_t)(b * 16 + h)) * 1024 + q) * 1024);
        float4 sv[8];
        float mx = -1e30f;
#pragma unroll
        for (int i = 0; i < 8; ++i) {
            float4 s = *(const float4*)&S[h * 1024 + lane * 4 + i * 128];
            float4 qk = qkr[lane + i * 32];
            s.x += qk.x; s.y += qk.y; s.z += qk.z; s.w += qk.w;
            sv[i] = s;
            mx = fmaxf(mx, fmaxf(fmaxf(s.x, s.y), fmaxf(s.z, s.w)));
        }
#pragma unroll
        for (int o = 16; o; o >>= 1) mx = fmaxf(mx, __shfl_xor_sync(0xffffffffu, mx, o));

        __half* prow = g_probs + (((size_t)(b * 16 + h)) * 1024 + q) * 1024;
        float sum = 0.f;
#pragma unroll
        for (int i = 0; i < 8; ++i) {
            float e0 = __expf(sv[i].x - mx);
            float e1 = __expf(sv[i].y - mx);
            float e2 = __expf(sv[i].z - mx);
            float e3 = __expf(sv[i].w - mx);
            sum += (e0 + e1) + (e2 + e3);
            __half2 p0 = __floats2half2_rn(e0, e1);
            __half2 p1 = __floats2half2_rn(e2, e3);
            uint2 pk;
            pk.x = reinterpret_cast<unsigned int&>(p0);
            pk.y = reinterpret_cast<unsigned int&>(p1);
            *(uint2*)(prow + lane * 4 + i * 128) = pk;
        }
#pragma unroll
        for (int o = 16; o; o >>= 1) sum += __shfl_xor_sync(0xffffffffu, sum, o);
        if (lane == 0) g_psum[(b * 16 + h) * 1024 + q] = sum;
    }
}

// ---------------- kernel 3: AV + gate ----------------
__global__ __launch_bounds__(256) void av_kernel() {
    __shared__ __half Ps[128][72];
    __shared__ float  Vs[64][36];
    int tid = threadIdx.x;
    int tx = tid & 7;
    int ty = tid >> 3;
    int bh = blockIdx.y;
    int b = bh >> 4, h = bh & 15;
    int q0 = blockIdx.x * 128;

    const __half* pb = g_probs + ((size_t)bh * 1024 + q0) * 1024;
    const float* vb = g_v + (size_t)b * 1024 * 512 + h * 32;

    float acc[4][4] = {};

    for (int kt = 0; kt < 16; ++kt) {
        __syncthreads();
#pragma unroll
        for (int u = 0; u < 4; ++u) {
            int id = tid + 256 * u;
            int row = id >> 3, c8 = id & 7;
            *(uint4*)&Ps[row][c8 * 8] = *(const uint4*)(pb + (size_t)row * 1024 + kt * 64 + c8 * 8);
        }
#pragma unroll
        for (int u = 0; u < 2; ++u) {
            int id = tid + 256 * u;
            int row = id >> 3, d4 = id & 7;
            *(float4*)&Vs[row][d4 * 4] = *(const float4*)(vb + (size_t)(kt * 64 + row) * 512 + d4 * 4);
        }
        __syncthreads();
#pragma unroll 4
        for (int k2 = 0; k2 < 32; ++k2) {
            int kk = k2 * 2;
            float4 v0 = *(const float4*)&Vs[kk][tx * 4];
            float4 v1 = *(const float4*)&Vs[kk + 1][tx * 4];
#pragma unroll
            for (int i = 0; i < 4; ++i) {
                float2 pf = __half22float2(*(const __half2*)&Ps[ty * 4 + i][kk]);
                acc[i][0] += pf.x * v0.x + pf.y * v1.x;
                acc[i][1] += pf.x * v0.y + pf.y * v1.y;
                acc[i][2] += pf.x * v0.z + pf.y * v1.z;
                acc[i][3] += pf.x * v0.w + pf.y * v1.w;
            }
        }
    }

#pragma unroll
    for (int i = 0; i < 4; ++i) {
        int q = q0 + ty * 4 + i;
        float inv = 1.0f / g_psum[bh * 1024 + q];
        size_t gi = ((size_t)(b * 1024 + q)) * 512 + h * 32 + tx * 4;
        float4 gv = *(const float4*)&g_g[gi];
        float4 o;
        o.x = acc[i][0] * inv * gv.x;
        o.y = acc[i][1] * inv * gv.y;
        o.z = acc[i][2] * inv * gv.z;
        o.w = acc[i][3] * inv * gv.w;
        *(float4*)&g_og[gi] = o;
    }
}

// ---------------- kernel 4: out = og @ w_o + b_o ----------------
__global__ __launch_bounds__(256) void out_kernel(const float* __restrict__ wo,
                                                  const float* __restrict__ bo,
                                                  float* __restrict__ out) {
    __shared__ float As[16][68];
    __shared__ float Bs[16][68];
    int bx = blockIdx.x;
    int by = blockIdx.y;
    int tid = threadIdx.x;
    int tx = tid & 15, ty = tid >> 4;
    int cl0 = bx * 64;
    float acc[4][4] = {};
    int aRow = tid >> 2, aK4 = (tid & 3) * 4;
    int bK = tid >> 4, bC4 = (tid & 15) * 4;
    for (int k0 = 0; k0 < 512; k0 += 16) {
        float4 va = *(const float4*)(g_og + (size_t)(by * 64 + aRow) * 512 + k0 + aK4);
        float4 vb = *(const float4*)(wo + (size_t)(k0 + bK) * 512 + cl0 + bC4);
        __syncthreads();
        As[aK4 + 0][aRow] = va.x;
        As[aK4 + 1][aRow] = va.y;
        As[aK4 + 2][aRow] = va.z;
        As[aK4 + 3][aRow] = va.w;
        *(float4*)&Bs[bK][bC4] = vb;
        __syncthreads();
#pragma unroll
        for (int kk = 0; kk < 16; ++kk) {
            float4 a = *(const float4*)&As[kk][ty * 4];
            float4 b = *(const float4*)&Bs[kk][tx * 4];
            float ar[4] = {a.x, a.y, a.z, a.w};
            float br[4] = {b.x, b.y, b.z, b.w};
#pragma unroll
            for (int i = 0; i < 4; ++i)
#pragma unroll
                for (int j = 0; j < 4; ++j) acc[i][j] += ar[i] * br[j];
        }
    }
#pragma unroll
    for (int i = 0; i < 4; ++i) {
        int row = by * 64 + ty * 4 + i;
#pragma unroll
        for (int j = 0; j < 4; ++j) {
            int col = cl0 + tx * 4 + j;
            out[(size_t)row * 512 + col] = acc[i][j] + bo[col];
        }
    }
}

// ---------------- launch ----------------
extern "C" void kernel_launch(void* const* d_in, const int* in_sizes, int n_in,
                              void* d_out, int out_size) {
    const float* m      = (const float*)d_in[0];
    const float* z      = (const float*)d_in[1];
    const float* mask   = (const float*)d_in[2];
    const float* ln_m_w = (const float*)d_in[3];
    const float* ln_m_b = (const float*)d_in[4];
    const float* ln_z_w = (const float*)d_in[5];
    const float* ln_z_b = (const float*)d_in[6];
    const float* w_z    = (const float*)d_in[7];
    const float* w_q    = (const float*)d_in[8];
    const float* w_k    = (const float*)d_in[9];
    const float* w_v    = (const float*)d_in[10];
    const float* w_g    = (const float*)d_in[11];
    const float* b_g    = (const float*)d_in[12];
    const float* w_o    = (const float*)d_in[13];
    const float* b_o    = (const float*)d_in[14];
    float* out = (float*)d_out;

    const int smem_bias = (16384 + 2 * ZTILE + 1024 + 32) * 4;   // 204,928 B
    cudaFuncSetAttribute(bias_attn_kernel,
                         cudaFuncAttributeMaxDynamicSharedMemorySize, smem_bias);

    ln_m_kernel<<<BB * NN, 128>>>(m, ln_m_w, ln_m_b);
    proj_kernel<<<dim3(32, 32), 256>>>(w_q, w_k, w_v, w_g, b_g);
    qk_kernel<<<dim3(64, 32), 512>>>();
    bias_attn_kernel<<<BB * NN, 512, smem_bias>>>(z, mask, ln_z_w, ln_z_b, w_z);
    av_kernel<<<dim3(8, 32), 256>>>();
    out_kernel<<<dim3(8, 32), 256>>>(w_o, b_o, out);
}

// round 12
// speedup vs baseline: 1.9211x; 1.1379x over previous
#include <cuda_runtime.h>
#include <cuda_fp16.h>
#include <cstdint>
#include <math.h>

#define BB 2
#define NN 1024
#define CIN 512
#define HH 16
#define DH 32
#define CZ 128

// ---------------- scratch (device globals; no allocation) ----------------
__device__ float g_mln[BB * NN * CIN];
__device__ float g_q[BB * NN * CIN];
__device__ float g_k[BB * NN * CIN];
__device__ float g_v[BB * NN * CIN];
__device__ float g_g[BB * NN * CIN];
__device__ float g_og[BB * NN * CIN];
__device__ float g_qk[(size_t)BB * HH * NN * NN];       // QK^T logits fp32 (128MB)
__device__ __half g_probs[(size_t)BB * HH * NN * NN];   // unnormalized exp fp16 (64MB)
__device__ float g_psum[BB * HH * NN];                  // softmax row sums

// ---------------- kernel 1a: LayerNorm(m) ----------------
__global__ __launch_bounds__(128) void ln_m_kernel(const float* __restrict__ m,
                                                   const float* __restrict__ w,
                                                   const float* __restrict__ b) {
    int row = blockIdx.x;
    int tid = threadIdx.x;
    const float4* mp = (const float4*)m + (size_t)row * 128;
    float4 x = mp[tid];
    float s = x.x + x.y + x.z + x.w;
    float q2 = x.x * x.x + x.y * x.y + x.z * x.z + x.w * x.w;
#pragma unroll
    for (int o = 16; o; o >>= 1) {
        s  += __shfl_xor_sync(0xffffffffu, s, o);
        q2 += __shfl_xor_sync(0xffffffffu, q2, o);
    }
    __shared__ float sS[4], sQ[4];
    __shared__ float s_mu, s_rstd;
    int wid = tid >> 5, lane = tid & 31;
    if (lane == 0) { sS[wid] = s; sQ[wid] = q2; }
    __syncthreads();
    if (tid == 0) {
        float ts = sS[0] + sS[1] + sS[2] + sS[3];
        float tq = sQ[0] + sQ[1] + sQ[2] + sQ[3];
        float mu = ts * (1.0f / 512.0f);
        float var = tq * (1.0f / 512.0f) - mu * mu;
        s_mu = mu;
        s_rstd = rsqrtf(var + 1e-5f);
    }
    __syncthreads();
    float mu = s_mu, rstd = s_rstd;
    float4 w4 = ((const float4*)w)[tid];
    float4 b4 = ((const float4*)b)[tid];
    float4 o;
    o.x = (x.x - mu) * rstd * w4.x + b4.x;
    o.y = (x.y - mu) * rstd * w4.y + b4.y;
    o.z = (x.z - mu) * rstd * w4.z + b4.z;
    o.w = (x.w - mu) * rstd * w4.w + b4.w;
    ((float4*)g_mln)[(size_t)row * 128 + tid] = o;
}

// ---------------- kernel 1b: projections q,k,v,g ----------------
__global__ __launch_bounds__(256) void proj_kernel(const float* __restrict__ wq,
                                                   const float* __restrict__ wk,
                                                   const float* __restrict__ wv,
                                                   const float* __restrict__ wg,
                                                   const float* __restrict__ bg) {
    __shared__ float As[16][68];
    __shared__ float Bs[16][68];
    int bx = blockIdx.x;
    int by = blockIdx.y;
    int tid = threadIdx.x;
    int tx = tid & 15, ty = tid >> 4;
    int sel = bx >> 3;
    int cl0 = (bx & 7) * 64;
    const float* W = (sel == 0) ? wq : (sel == 1) ? wk : (sel == 2) ? wv : wg;
    float acc[4][4] = {};
    int aRow = tid >> 2, aK4 = (tid & 3) * 4;
    int bK = tid >> 4, bC4 = (tid & 15) * 4;
    for (int k0 = 0; k0 < 512; k0 += 16) {
        float4 va = *(const float4*)(g_mln + (size_t)(by * 64 + aRow) * 512 + k0 + aK4);
        float4 vb = *(const float4*)(W + (size_t)(k0 + bK) * 512 + cl0 + bC4);
        __syncthreads();
        As[aK4 + 0][aRow] = va.x;
        As[aK4 + 1][aRow] = va.y;
        As[aK4 + 2][aRow] = va.z;
        As[aK4 + 3][aRow] = va.w;
        *(float4*)&Bs[bK][bC4] = vb;
        __syncthreads();
#pragma unroll
        for (int kk = 0; kk < 16; ++kk) {
            float4 a = *(const float4*)&As[kk][ty * 4];
            float4 b = *(const float4*)&Bs[kk][tx * 4];
            float ar[4] = {a.x, a.y, a.z, a.w};
            float br[4] = {b.x, b.y, b.z, b.w};
#pragma unroll
            for (int i = 0; i < 4; ++i)
#pragma unroll
                for (int j = 0; j < 4; ++j) acc[i][j] += ar[i] * br[j];
        }
    }
    const float qscale = 0.17677669529663687f;
#pragma unroll
    for (int i = 0; i < 4; ++i) {
        int row = by * 64 + ty * 4 + i;
#pragma unroll
        for (int j = 0; j < 4; ++j) {
            int col = cl0 + tx * 4 + j;
            size_t oidx = (size_t)row * 512 + col;
            float v = acc[i][j];
            if (sel == 0)      g_q[oidx] = v * qscale;
            else if (sel == 1) g_k[oidx] = v;
            else if (sel == 2) g_v[oidx] = v;
            else               g_g[oidx] = 1.0f / (1.0f + __expf(-(v + bg[col])));
        }
    }
}

// ---------------- kernel 1c: qk[b,h,q,k] = q . k  (batched GEMM) ----------------
__global__ __launch_bounds__(512) void qk_kernel() {
    __shared__ float Qs[128][36];
    __shared__ float Ks[128][36];
    int tid = threadIdx.x;
    int bh = blockIdx.y;
    int b = bh >> 4, h = bh & 15;
    int q0 = (blockIdx.x >> 3) * 128;
    int k0 = (blockIdx.x & 7) * 128;
    const float* qb = g_q + (size_t)(b * 1024) * 512 + h * 32;
    const float* kb = g_k + (size_t)(b * 1024) * 512 + h * 32;
#pragma unroll
    for (int u = 0; u < 2; ++u) {
        int fid = tid + 512 * u;
        int row = fid >> 3, d4 = (fid & 7) * 4;
        *(float4*)&Qs[row][d4] = *(const float4*)(qb + (size_t)(q0 + row) * 512 + d4);
        *(float4*)&Ks[row][d4] = *(const float4*)(kb + (size_t)(k0 + row) * 512 + d4);
    }
    __syncthreads();
    int tx = tid & 15, ty = tid >> 4;
    float acc[4][8] = {};
#pragma unroll
    for (int d4 = 0; d4 < 8; ++d4) {
        float4 av[4], bv[8];
#pragma unroll
        for (int i = 0; i < 4; ++i) av[i] = *(const float4*)&Qs[ty + 32 * i][d4 * 4];
#pragma unroll
        for (int j = 0; j < 8; ++j) bv[j] = *(const float4*)&Ks[tx + 16 * j][d4 * 4];
#pragma unroll
        for (int i = 0; i < 4; ++i)
#pragma unroll
            for (int j = 0; j < 8; ++j)
                acc[i][j] += av[i].x * bv[j].x + av[i].y * bv[j].y +
                             av[i].z * bv[j].z + av[i].w * bv[j].w;
    }
    float* ob = g_qk + ((size_t)bh * 1024 + q0) * 1024 + k0;
#pragma unroll
    for (int i = 0; i < 4; ++i)
#pragma unroll
        for (int j = 0; j < 8; ++j)
            ob[(size_t)(ty + 32 * i) * 1024 + tx + 16 * j] = acc[i][j];
}

// ---------------- kernel 2: fused pair-bias + (+qk) + softmax -> fp16 probs ----------------
// dyn smem floats: S[16384] | wzw2[1024 half2 = 1024 floats] | s1[16] | c0[16]
__global__ __launch_bounds__(512, 1) void bias_attn_kernel(const float* __restrict__ z,
                                                           const float* __restrict__ mask,
                                                           const float* __restrict__ lzw,
                                                           const float* __restrict__ lzb,
                                                           const float* __restrict__ wz) {
    extern __shared__ float smbuf[];
    float* S = smbuf;                                     // 16 x 1024
    __half2* wzw2 = (__half2*)(smbuf + 16384);            // [c2][h] head weights per c-pair
    float* s1 = smbuf + 16384 + 1024;
    float* c0 = s1 + 16;

    int tid = threadIdx.x;
    int bq = blockIdx.x;
    int b = bq >> 10, q = bq & 1023;

    // prologue: pack c-pair weights wzw2[c2*16+h] = ((lzw*wz)[2c2][h], (lzw*wz)[2c2+1][h])
    for (int idx = tid; idx < 1024; idx += 512) {
        int c2 = idx >> 4, h = idx & 15;
        wzw2[idx] = __floats2half2_rn(lzw[2 * c2] * wz[(2 * c2) * 16 + h],
                                      lzw[2 * c2 + 1] * wz[(2 * c2 + 1) * 16 + h]);
    }
    if (tid < 16) {
        float a = 0.f, bb2 = 0.f;
#pragma unroll 4
        for (int c = 0; c < 128; ++c) {
            a   += lzw[c] * wz[c * 16 + tid];
            bb2 += lzb[c] * wz[c * 16 + tid];
        }
        s1[tid] = a;
        c0[tid] = bb2;
    }
    __syncthreads();

    // ---- phase A: direct-LDG z streaming; 4 lanes per row; HFMA2 head-pair dots ----
    const float* zrow = z + (size_t)bq * 1024 * 128;   // this (b,q)'s z[k][c] slab
    int w = tid >> 5, lane = tid & 31;
    int qd = lane & 3;            // c-quarter within 16-chunk
    int rsub = lane >> 2;         // row within 8-row warp pass
    int h0 = qd * 4;              // heads this lane writes

    float s1r0 = s1[h0 + 0], s1r1 = s1[h0 + 1], s1r2 = s1[h0 + 2], s1r3 = s1[h0 + 3];
    float c0r0 = c0[h0 + 0], c0r1 = c0[h0 + 1], c0r2 = c0[h0 + 2], c0r3 = c0[h0 + 3];
    const __half2 hz = __float2half2_rn(0.f);

#pragma unroll 1
    for (int p = 0; p < 8; ++p) {
        int k = w * 64 + p * 8 + rsub;
        const float4* zk = (const float4*)(zrow + (size_t)k * 128);

        __half2 acc[16];
#pragma unroll
        for (int hh = 0; hh < 16; ++hh) acc[hh] = hz;
        float sm = 0.f, sq = 0.f;

#pragma unroll
        for (int j = 0; j < 8; ++j) {
            // lane reads c = j*16 + qd*4 .. +3 ; 4 lanes of a row cover 64B contiguous
            float4 x = zk[j * 4 + qd];
            sm += (x.x + x.y) + (x.z + x.w);
            sq += x.x * x.x; sq += x.y * x.y; sq += x.z * x.z; sq += x.w * x.w;
            __half2 xa = __floats2half2_rn(x.x, x.y);
            __half2 xb = __floats2half2_rn(x.z, x.w);
            const float4* wvp = (const float4*)(wzw2 + (size_t)(j * 8 + qd * 2) * 16);
#pragma unroll
            for (int u = 0; u < 4; ++u) {
                float4 f = wvp[u];
                const __half2* wp = (const __half2*)&f;
                acc[u * 4 + 0] = __hfma2(xa, wp[0], acc[u * 4 + 0]);
                acc[u * 4 + 1] = __hfma2(xa, wp[1], acc[u * 4 + 1]);
                acc[u * 4 + 2] = __hfma2(xa, wp[2], acc[u * 4 + 2]);
                acc[u * 4 + 3] = __hfma2(xa, wp[3], acc[u * 4 + 3]);
            }
#pragma unroll
            for (int u = 0; u < 4; ++u) {
                float4 f = wvp[4 + u];
                const __half2* wp = (const __half2*)&f;
                acc[u * 4 + 0] = __hfma2(xb, wp[0], acc[u * 4 + 0]);
                acc[u * 4 + 1] = __hfma2(xb, wp[1], acc[u * 4 + 1]);
                acc[u * 4 + 2] = __hfma2(xb, wp[2], acc[u * 4 + 2]);
                acc[u * 4 + 3] = __hfma2(xb, wp[3], acc[u * 4 + 3]);
            }
        }

        // fold fp16 pairs -> fp32, butterfly over the 4 lanes of this row
        float dred[16];
#pragma unroll
        for (int hh = 0; hh < 16; ++hh) {
            float2 f = __half22float2(acc[hh]);
            dred[hh] = f.x + f.y;
        }
#pragma unroll
        for (int hh = 0; hh < 16; ++hh) {
            dred[hh] += __shfl_xor_sync(0xffffffffu, dred[hh], 1);
            dred[hh] += __shfl_xor_sync(0xffffffffu, dred[hh], 2);
        }
        sm += __shfl_xor_sync(0xffffffffu, sm, 1);
        sm += __shfl_xor_sync(0xffffffffu, sm, 2);
        sq += __shfl_xor_sync(0xffffffffu, sq, 1);
        sq += __shfl_xor_sync(0xffffffffu, sq, 2);

        float mu = sm * (1.0f / 128.0f);
        float rstd = rsqrtf(sq * (1.0f / 128.0f) - mu * mu + 1e-5f);
        float mb = 1e9f * (mask[b * 1024 + k] - 1.0f);
        S[(h0 + 0) * 1024 + k] = rstd * (dred[h0 + 0] - mu * s1r0) + c0r0 + mb;
        S[(h0 + 1) * 1024 + k] = rstd * (dred[h0 + 1] - mu * s1r1) + c0r1 + mb;
        S[(h0 + 2) * 1024 + k] = rstd * (dred[h0 + 2] - mu * s1r2) + c0r2 + mb;
        S[(h0 + 3) * 1024 + k] = rstd * (dred[h0 + 3] - mu * s1r3) + c0r3 + mb;
    }
    __syncthreads();

    // ---- phase B: warp w owns head w: add qk logits, softmax, fp16 probs ----
    {
        int h = w;
        const float4* qkr = (const float4*)(g_qk + (((size_t)(b * 16 + h)) * 1024 + q) * 1024);
        float4 sv[8];
        float mx = -1e30f;
#pragma unroll
        for (int i = 0; i < 8; ++i) {
            float4 s = *(const float4*)&S[h * 1024 + lane * 4 + i * 128];
            float4 qk = qkr[lane + i * 32];
            s.x += qk.x; s.y += qk.y; s.z += qk.z; s.w += qk.w;
            sv[i] = s;
            mx = fmaxf(mx, fmaxf(fmaxf(s.x, s.y), fmaxf(s.z, s.w)));
        }
#pragma unroll
        for (int o = 16; o; o >>= 1) mx = fmaxf(mx, __shfl_xor_sync(0xffffffffu, mx, o));

        __half* prow = g_probs + (((size_t)(b * 16 + h)) * 1024 + q) * 1024;
        float sum = 0.f;
#pragma unroll
        for (int i = 0; i < 8; ++i) {
            float e0 = __expf(sv[i].x - mx);
            float e1 = __expf(sv[i].y - mx);
            float e2 = __expf(sv[i].z - mx);
            float e3 = __expf(sv[i].w - mx);
            sum += (e0 + e1) + (e2 + e3);
            __half2 p0 = __floats2half2_rn(e0, e1);
            __half2 p1 = __floats2half2_rn(e2, e3);
            uint2 pk;
            pk.x = reinterpret_cast<unsigned int&>(p0);
            pk.y = reinterpret_cast<unsigned int&>(p1);
            *(uint2*)(prow + lane * 4 + i * 128) = pk;
        }
#pragma unroll
        for (int o = 16; o; o >>= 1) sum += __shfl_xor_sync(0xffffffffu, sum, o);
        if (lane == 0) g_psum[(b * 16 + h) * 1024 + q] = sum;
    }
}

// ---------------- kernel 3: AV + gate ----------------
__global__ __launch_bounds__(256) void av_kernel() {
    __shared__ __half Ps[128][72];
    __shared__ float  Vs[64][36];
    int tid = threadIdx.x;
    int tx = tid & 7;
    int ty = tid >> 3;
    int bh = blockIdx.y;
    int b = bh >> 4, h = bh & 15;
    int q0 = blockIdx.x * 128;

    const __half* pb = g_probs + ((size_t)bh * 1024 + q0) * 1024;
    const float* vb = g_v + (size_t)b * 1024 * 512 + h * 32;

    float acc[4][4] = {};

    for (int kt = 0; kt < 16; ++kt) {
        __syncthreads();
#pragma unroll
        for (int u = 0; u < 4; ++u) {
            int id = tid + 256 * u;
            int row = id >> 3, c8 = id & 7;
            *(uint4*)&Ps[row][c8 * 8] = *(const uint4*)(pb + (size_t)row * 1024 + kt * 64 + c8 * 8);
        }
#pragma unroll
        for (int u = 0; u < 2; ++u) {
            int id = tid + 256 * u;
            int row = id >> 3, d4 = id & 7;
            *(float4*)&Vs[row][d4 * 4] = *(const float4*)(vb + (size_t)(kt * 64 + row) * 512 + d4 * 4);
        }
        __syncthreads();
#pragma unroll 4
        for (int k2 = 0; k2 < 32; ++k2) {
            int kk = k2 * 2;
            float4 v0 = *(const float4*)&Vs[kk][tx * 4];
            float4 v1 = *(const float4*)&Vs[kk + 1][tx * 4];
#pragma unroll
            for (int i = 0; i < 4; ++i) {
                float2 pf = __half22float2(*(const __half2*)&Ps[ty * 4 + i][kk]);
                acc[i][0] += pf.x * v0.x + pf.y * v1.x;
                acc[i][1] += pf.x * v0.y + pf.y * v1.y;
                acc[i][2] += pf.x * v0.z + pf.y * v1.z;
                acc[i][3] += pf.x * v0.w + pf.y * v1.w;
            }
        }
    }

#pragma unroll
    for (int i = 0; i < 4; ++i) {
        int q = q0 + ty * 4 + i;
        float inv = 1.0f / g_psum[bh * 1024 + q];
        size_t gi = ((size_t)(b * 1024 + q)) * 512 + h * 32 + tx * 4;
        float4 gv = *(const float4*)&g_g[gi];
        float4 o;
        o.x = acc[i][0] * inv * gv.x;
        o.y = acc[i][1] * inv * gv.y;
        o.z = acc[i][2] * inv * gv.z;
        o.w = acc[i][3] * inv * gv.w;
        *(float4*)&g_og[gi] = o;
    }
}

// ---------------- kernel 4: out = og @ w_o + b_o ----------------
__global__ __launch_bounds__(256) void out_kernel(const float* __restrict__ wo,
                                                  const float* __restrict__ bo,
                                                  float* __restrict__ out) {
    __shared__ float As[16][68];
    __shared__ float Bs[16][68];
    int bx = blockIdx.x;
    int by = blockIdx.y;
    int tid = threadIdx.x;
    int tx = tid & 15, ty = tid >> 4;
    int cl0 = bx * 64;
    float acc[4][4] = {};
    int aRow = tid >> 2, aK4 = (tid & 3) * 4;
    int bK = tid >> 4, bC4 = (tid & 15) * 4;
    for (int k0 = 0; k0 < 512; k0 += 16) {
        float4 va = *(const float4*)(g_og + (size_t)(by * 64 + aRow) * 512 + k0 + aK4);
        float4 vb = *(const float4*)(wo + (size_t)(k0 + bK) * 512 + cl0 + bC4);
        __syncthreads();
        As[aK4 + 0][aRow] = va.x;
        As[aK4 + 1][aRow] = va.y;
        As[aK4 + 2][aRow] = va.z;
        As[aK4 + 3][aRow] = va.w;
        *(float4*)&Bs[bK][bC4] = vb;
        __syncthreads();
#pragma unroll
        for (int kk = 0; kk < 16; ++kk) {
            float4 a = *(const float4*)&As[kk][ty * 4];
            float4 b = *(const float4*)&Bs[kk][tx * 4];
            float ar[4] = {a.x, a.y, a.z, a.w};
            float br[4] = {b.x, b.y, b.z, b.w};
#pragma unroll
            for (int i = 0; i < 4; ++i)
#pragma unroll
                for (int j = 0; j < 4; ++j) acc[i][j] += ar[i] * br[j];
        }
    }
#pragma unroll
    for (int i = 0; i < 4; ++i) {
        int row = by * 64 + ty * 4 + i;
#pragma unroll
        for (int j = 0; j < 4; ++j) {
            int col = cl0 + tx * 4 + j;
            out[(size_t)row * 512 + col] = acc[i][j] + bo[col];
        }
    }
}

// ---------------- launch ----------------
extern "C" void kernel_launch(void* const* d_in, const int* in_sizes, int n_in,
                              void* d_out, int out_size) {
    const float* m      = (const float*)d_in[0];
    const float* z      = (const float*)d_in[1];
    const float* mask   = (const float*)d_in[2];
    const float* ln_m_w = (const float*)d_in[3];
    const float* ln_m_b = (const float*)d_in[4];
    const float* ln_z_w = (const float*)d_in[5];
    const float* ln_z_b = (const float*)d_in[6];
    const float* w_z    = (const float*)d_in[7];
    const float* w_q    = (const float*)d_in[8];
    const float* w_k    = (const float*)d_in[9];
    const float* w_v    = (const float*)d_in[10];
    const float* w_g    = (const float*)d_in[11];
    const float* b_g    = (const float*)d_in[12];
    const float* w_o    = (const float*)d_in[13];
    const float* b_o    = (const float*)d_in[14];
    float* out = (float*)d_out;

    const int smem_bias = (16384 + 1024 + 32) * 4;   // 69760 B
    cudaFuncSetAttribute(bias_attn_kernel,
                         cudaFuncAttributeMaxDynamicSharedMemorySize, smem_bias);

    ln_m_kernel<<<BB * NN, 128>>>(m, ln_m_w, ln_m_b);
    proj_kernel<<<dim3(32, 32), 256>>>(w_q, w_k, w_v, w_g, b_g);
    qk_kernel<<<dim3(64, 32), 512>>>();
    bias_attn_kernel<<<BB * NN, 512, smem_bias>>>(z, mask, ln_z_w, ln_z_b, w_z);
    av_kernel<<<dim3(8, 32), 256>>>();
    out_kernel<<<dim3(8, 32), 256>>>(w_o, b_o, out);
}

// round 15
// speedup vs baseline: 2.2724x; 1.1829x over previous
#include <cuda_runtime.h>
#include <cuda_fp16.h>
#include <cstdint>
#include <math.h>

#define BB 2
#define NN 1024
#define CIN 512
#define HH 16
#define DH 32
#define CZ 128

// ---------------- scratch (device globals; no allocation) ----------------
__device__ float g_mln[BB * NN * CIN];
__device__ float g_q[BB * NN * CIN];
__device__ float g_k[BB * NN * CIN];
__device__ float g_v[BB * NN * CIN];
__device__ float g_g[BB * NN * CIN];
__device__ float g_og[BB * NN * CIN];
__device__ float g_qk[(size_t)BB * HH * NN * NN];       // QK^T logits fp32 (128MB)
__device__ __half g_probs[(size_t)BB * HH * NN * NN];   // unnormalized exp fp16 (64MB)
__device__ float g_psum[BB * HH * NN];                  // softmax row sums

// ---------------- kernel 1a: LayerNorm(m) ----------------
__global__ __launch_bounds__(128) void ln_m_kernel(const float* __restrict__ m,
                                                   const float* __restrict__ w,
                                                   const float* __restrict__ b) {
    int row = blockIdx.x;
    int tid = threadIdx.x;
    const float4* mp = (const float4*)m + (size_t)row * 128;
    float4 x = mp[tid];
    float s = x.x + x.y + x.z + x.w;
    float q2 = x.x * x.x + x.y * x.y + x.z * x.z + x.w * x.w;
#pragma unroll
    for (int o = 16; o; o >>= 1) {
        s  += __shfl_xor_sync(0xffffffffu, s, o);
        q2 += __shfl_xor_sync(0xffffffffu, q2, o);
    }
    __shared__ float sS[4], sQ[4];
    __shared__ float s_mu, s_rstd;
    int wid = tid >> 5, lane = tid & 31;
    if (lane == 0) { sS[wid] = s; sQ[wid] = q2; }
    __syncthreads();
    if (tid == 0) {
        float ts = sS[0] + sS[1] + sS[2] + sS[3];
        float tq = sQ[0] + sQ[1] + sQ[2] + sQ[3];
        float mu = ts * (1.0f / 512.0f);
        float var = tq * (1.0f / 512.0f) - mu * mu;
        s_mu = mu;
        s_rstd = rsqrtf(var + 1e-5f);
    }
    __syncthreads();
    float mu = s_mu, rstd = s_rstd;
    float4 w4 = ((const float4*)w)[tid];
    float4 b4 = ((const float4*)b)[tid];
    float4 o;
    o.x = (x.x - mu) * rstd * w4.x + b4.x;
    o.y = (x.y - mu) * rstd * w4.y + b4.y;
    o.z = (x.z - mu) * rstd * w4.z + b4.z;
    o.w = (x.w - mu) * rstd * w4.w + b4.w;
    ((float4*)g_mln)[(size_t)row * 128 + tid] = o;
}

// ---------------- kernel 1b: projections q,k,v,g ----------------
__global__ __launch_bounds__(256) void proj_kernel(const float* __restrict__ wq,
                                                   const float* __restrict__ wk,
                                                   const float* __restrict__ wv,
                                                   const float* __restrict__ wg,
                                                   const float* __restrict__ bg) {
    __shared__ float As[16][68];
    __shared__ float Bs[16][68];
    int bx = blockIdx.x;
    int by = blockIdx.y;
    int tid = threadIdx.x;
    int tx = tid & 15, ty = tid >> 4;
    int sel = bx >> 3;
    int cl0 = (bx & 7) * 64;
    const float* W = (sel == 0) ? wq : (sel == 1) ? wk : (sel == 2) ? wv : wg;
    float acc[4][4] = {};
    int aRow = tid >> 2, aK4 = (tid & 3) * 4;
    int bK = tid >> 4, bC4 = (tid & 15) * 4;
    for (int k0 = 0; k0 < 512; k0 += 16) {
        float4 va = *(const float4*)(g_mln + (size_t)(by * 64 + aRow) * 512 + k0 + aK4);
        float4 vb = *(const float4*)(W + (size_t)(k0 + bK) * 512 + cl0 + bC4);
        __syncthreads();
        As[aK4 + 0][aRow] = va.x;
        As[aK4 + 1][aRow] = va.y;
        As[aK4 + 2][aRow] = va.z;
        As[aK4 + 3][aRow] = va.w;
        *(float4*)&Bs[bK][bC4] = vb;
        __syncthreads();
#pragma unroll
        for (int kk = 0; kk < 16; ++kk) {
            float4 a = *(const float4*)&As[kk][ty * 4];
            float4 b = *(const float4*)&Bs[kk][tx * 4];
            float ar[4] = {a.x, a.y, a.z, a.w};
            float br[4] = {b.x, b.y, b.z, b.w};
#pragma unroll
            for (int i = 0; i < 4; ++i)
#pragma unroll
                for (int j = 0; j < 4; ++j) acc[i][j] += ar[i] * br[j];
        }
    }
    const float qscale = 0.17677669529663687f;
#pragma unroll
    for (int i = 0; i < 4; ++i) {
        int row = by * 64 + ty * 4 + i;
#pragma unroll
        for (int j = 0; j < 4; ++j) {
            int col = cl0 + tx * 4 + j;
            size_t oidx = (size_t)row * 512 + col;
            float v = acc[i][j];
            if (sel == 0)      g_q[oidx] = v * qscale;
            else if (sel == 1) g_k[oidx] = v;
            else if (sel == 2) g_v[oidx] = v;
            else               g_g[oidx] = 1.0f / (1.0f + __expf(-(v + bg[col])));
        }
    }
}

// ---------------- kernel 1c: qk[b,h,q,k] = q . k  (batched GEMM) ----------------
__global__ __launch_bounds__(512) void qk_kernel() {
    __shared__ float Qs[128][36];
    __shared__ float Ks[128][36];
    int tid = threadIdx.x;
    int bh = blockIdx.y;
    int b = bh >> 4, h = bh & 15;
    int q0 = (blockIdx.x >> 3) * 128;
    int k0 = (blockIdx.x & 7) * 128;
    const float* qb = g_q + (size_t)(b * 1024) * 512 + h * 32;
    const float* kb = g_k + (size_t)(b * 1024) * 512 + h * 32;
#pragma unroll
    for (int u = 0; u < 2; ++u) {
        int fid = tid + 512 * u;
        int row = fid >> 3, d4 = (fid & 7) * 4;
        *(float4*)&Qs[row][d4] = *(const float4*)(qb + (size_t)(q0 + row) * 512 + d4);
        *(float4*)&Ks[row][d4] = *(const float4*)(kb + (size_t)(k0 + row) * 512 + d4);
    }
    __syncthreads();
    int tx = tid & 15, ty = tid >> 4;
    float acc[4][8] = {};
#pragma unroll
    for (int d4 = 0; d4 < 8; ++d4) {
        float4 av[4], bv[8];
#pragma unroll
        for (int i = 0; i < 4; ++i) av[i] = *(const float4*)&Qs[ty + 32 * i][d4 * 4];
#pragma unroll
        for (int j = 0; j < 8; ++j) bv[j] = *(const float4*)&Ks[tx + 16 * j][d4 * 4];
#pragma unroll
        for (int i = 0; i < 4; ++i)
#pragma unroll
            for (int j = 0; j < 8; ++j)
                acc[i][j] += av[i].x * bv[j].x + av[i].y * bv[j].y +
                             av[i].z * bv[j].z + av[i].w * bv[j].w;
    }
    float* ob = g_qk + ((size_t)bh * 1024 + q0) * 1024 + k0;
#pragma unroll
    for (int i = 0; i < 4; ++i)
#pragma unroll
        for (int j = 0; j < 8; ++j)
            ob[(size_t)(ty + 32 * i) * 1024 + tx + 16 * j] = acc[i][j];
}

// ---------------- kernel 2: fused pair-bias + (+qk) + softmax -> fp16 probs ----------------
// dyn smem floats: S[16384] | wzs[4*264 half2 = 1056 floats] | s1[16] | c0[16]
// wzs layout: [qd][j][pair][h] with qd-stride 264 half2 (8-bank skew -> conflict-free)
#define WQD 264
__global__ __launch_bounds__(512, 1) void bias_attn_kernel(const float* __restrict__ z,
                                                           const float* __restrict__ mask,
                                                           const float* __restrict__ lzw,
                                                           const float* __restrict__ lzb,
                                                           const float* __restrict__ wz) {
    extern __shared__ float smbuf[];
    float* S = smbuf;                                     // 16 x 1024
    __half2* wzs = (__half2*)(smbuf + 16384);             // 4*264 half2 = 1056 floats
    float* s1 = smbuf + 16384 + 1056;
    float* c0 = s1 + 16;

    int tid = threadIdx.x;
    int bq = blockIdx.x;
    int b = bq >> 10, q = bq & 1023;

    // prologue: pack head-pair weights into skewed [qd][j][pair][h] layout
    for (int i = tid; i < 1024; i += 512) {
        int h = i & 15;
        int pair = (i >> 4) & 1;
        int j = (i >> 5) & 7;
        int qdp = i >> 8;
        int cc = j * 16 + qdp * 4 + pair * 2;
        wzs[qdp * WQD + j * 32 + pair * 16 + h] =
            __floats2half2_rn(lzw[cc] * wz[cc * 16 + h],
                              lzw[cc + 1] * wz[(cc + 1) * 16 + h]);
    }
    if (tid < 16) {
        float a = 0.f, bb2 = 0.f;
#pragma unroll 4
        for (int c = 0; c < 128; ++c) {
            a   += lzw[c] * wz[c * 16 + tid];
            bb2 += lzb[c] * wz[c * 16 + tid];
        }
        s1[tid] = a;
        c0[tid] = bb2;
    }
    __syncthreads();

    // ---- phase A: direct-LDG z streaming; 4 lanes per row; HFMA2 head-pair dots ----
    const float* zrow = z + (size_t)bq * 1024 * 128;   // this (b,q)'s z[k][c] slab
    int w = tid >> 5, lane = tid & 31;
    int qd = lane & 3;            // c-quarter within 16-chunk
    int rsub = lane >> 2;         // row within 8-row warp pass
    int h0 = qd * 4;              // heads this lane writes

    float s1r0 = s1[h0 + 0], s1r1 = s1[h0 + 1], s1r2 = s1[h0 + 2], s1r3 = s1[h0 + 3];
    float c0r0 = c0[h0 + 0], c0r1 = c0[h0 + 1], c0r2 = c0[h0 + 2], c0r3 = c0[h0 + 3];
    const __half2 hz = __float2half2_rn(0.f);
    const __half2* wbase = wzs + qd * WQD;

#pragma unroll 1
    for (int p = 0; p < 8; ++p) {
        int k = w * 64 + p * 8 + rsub;
        const float4* zk = (const float4*)(zrow + (size_t)k * 128);

        __half2 acc[16];
#pragma unroll
        for (int hh = 0; hh < 16; ++hh) acc[hh] = hz;
        float sm = 0.f, sq = 0.f;

#pragma unroll
        for (int j = 0; j < 8; ++j) {
            // lane reads c = j*16 + qd*4 .. +3 ; 4 lanes of a row cover 64B contiguous
            float4 x = zk[j * 4 + qd];
            sm += (x.x + x.y) + (x.z + x.w);
            sq += x.x * x.x; sq += x.y * x.y; sq += x.z * x.z; sq += x.w * x.w;
            __half2 xa = __floats2half2_rn(x.x, x.y);
            __half2 xb = __floats2half2_rn(x.z, x.w);
            const float4* wvp = (const float4*)(wbase + j * 32);
#pragma unroll
            for (int u = 0; u < 4; ++u) {
                float4 f = wvp[u];                       // pair a, heads u*4..u*4+3
                const __half2* wp = (const __half2*)&f;
                acc[u * 4 + 0] = __hfma2(xa, wp[0], acc[u * 4 + 0]);
                acc[u * 4 + 1] = __hfma2(xa, wp[1], acc[u * 4 + 1]);
                acc[u * 4 + 2] = __hfma2(xa, wp[2], acc[u * 4 + 2]);
                acc[u * 4 + 3] = __hfma2(xa, wp[3], acc[u * 4 + 3]);
            }
#pragma unroll
            for (int u = 0; u < 4; ++u) {
                float4 f = wvp[4 + u];                   // pair b, heads u*4..u*4+3
                const __half2* wp = (const __half2*)&f;
                acc[u * 4 + 0] = __hfma2(xb, wp[0], acc[u * 4 + 0]);
                acc[u * 4 + 1] = __hfma2(xb, wp[1], acc[u * 4 + 1]);
                acc[u * 4 + 2] = __hfma2(xb, wp[2], acc[u * 4 + 2]);
                acc[u * 4 + 3] = __hfma2(xb, wp[3], acc[u * 4 + 3]);
            }
        }

        // fold fp16 pairs -> fp32, butterfly over the 4 lanes of this row
        float dred[16];
#pragma unroll
        for (int hh = 0; hh < 16; ++hh) {
            float2 f = __half22float2(acc[hh]);
            dred[hh] = f.x + f.y;
        }
#pragma unroll
        for (int hh = 0; hh < 16; ++hh) {
            dred[hh] += __shfl_xor_sync(0xffffffffu, dred[hh], 1);
            dred[hh] += __shfl_xor_sync(0xffffffffu, dred[hh], 2);
        }
        sm += __shfl_xor_sync(0xffffffffu, sm, 1);
        sm += __shfl_xor_sync(0xffffffffu, sm, 2);
        sq += __shfl_xor_sync(0xffffffffu, sq, 1);
        sq += __shfl_xor_sync(0xffffffffu, sq, 2);

        float mu = sm * (1.0f / 128.0f);
        float rstd = rsqrtf(sq * (1.0f / 128.0f) - mu * mu + 1e-5f);
        float mb = 1e9f * (mask[b * 1024 + k] - 1.0f);
        S[(h0 + 0) * 1024 + k] = rstd * (dred[h0 + 0] - mu * s1r0) + c0r0 + mb;
        S[(h0 + 1) * 1024 + k] = rstd * (dred[h0 + 1] - mu * s1r1) + c0r1 + mb;
        S[(h0 + 2) * 1024 + k] = rstd * (dred[h0 + 2] - mu * s1r2) + c0r2 + mb;
        S[(h0 + 3) * 1024 + k] = rstd * (dred[h0 + 3] - mu * s1r3) + c0r3 + mb;
    }
    __syncthreads();

    // ---- phase B: warp w owns head w: add qk logits, softmax, fp16 probs ----
    {
        int h = w;
        const float4* qkr = (const float4*)(g_qk + (((size_t)(b * 16 + h)) * 1024 + q) * 1024);
        float4 sv[8];
        float mx = -1e30f;
#pragma unroll
        for (int i = 0; i < 8; ++i) {
            float4 s = *(const float4*)&S[h * 1024 + lane * 4 + i * 128];
            float4 qk = qkr[lane + i * 32];
            s.x += qk.x; s.y += qk.y; s.z += qk.z; s.w += qk.w;
            sv[i] = s;
            mx = fmaxf(mx, fmaxf(fmaxf(s.x, s.y), fmaxf(s.z, s.w)));
        }
#pragma unroll
        for (int o = 16; o; o >>= 1) mx = fmaxf(mx, __shfl_xor_sync(0xffffffffu, mx, o));

        __half* prow = g_probs + (((size_t)(b * 16 + h)) * 1024 + q) * 1024;
        float sum = 0.f;
#pragma unroll
        for (int i = 0; i < 8; ++i) {
            float e0 = __expf(sv[i].x - mx);
            float e1 = __expf(sv[i].y - mx);
            float e2 = __expf(sv[i].z - mx);
            float e3 = __expf(sv[i].w - mx);
            sum += (e0 + e1) + (e2 + e3);
            __half2 p0 = __floats2half2_rn(e0, e1);
            __half2 p1 = __floats2half2_rn(e2, e3);
            uint2 pk;
            pk.x = reinterpret_cast<unsigned int&>(p0);
            pk.y = reinterpret_cast<unsigned int&>(p1);
            *(uint2*)(prow + lane * 4 + i * 128) = pk;
        }
#pragma unroll
        for (int o = 16; o; o >>= 1) sum += __shfl_xor_sync(0xffffffffu, sum, o);
        if (lane == 0) g_psum[(b * 16 + h) * 1024 + q] = sum;
    }
}

// ---------------- kernel 3: AV + gate ----------------
__global__ __launch_bounds__(256) void av_kernel() {
    __shared__ __half Ps[128][72];
    __shared__ float  Vs[64][36];
    int tid = threadIdx.x;
    int tx = tid & 7;
    int ty = tid >> 3;
    int bh = blockIdx.y;
    int b = bh >> 4, h = bh & 15;
    int q0 = blockIdx.x * 128;

    const __half* pb = g_probs + ((size_t)bh * 1024 + q0) * 1024;
    const float* vb = g_v + (size_t)b * 1024 * 512 + h * 32;

    float acc[4][4] = {};

    for (int kt = 0; kt < 16; ++kt) {
        __syncthreads();
#pragma unroll
        for (int u = 0; u < 4; ++u) {
            int id = tid + 256 * u;
            int row = id >> 3, c8 = id & 7;
            *(uint4*)&Ps[row][c8 * 8] = *(const uint4*)(pb + (size_t)row * 1024 + kt * 64 + c8 * 8);
        }
#pragma unroll
        for (int u = 0; u < 2; ++u) {
            int id = tid + 256 * u;
            int row = id >> 3, d4 = id & 7;
            *(float4*)&Vs[row][d4 * 4] = *(const float4*)(vb + (size_t)(kt * 64 + row) * 512 + d4 * 4);
        }
        __syncthreads();
#pragma unroll 4
        for (int k2 = 0; k2 < 32; ++k2) {
            int kk = k2 * 2;
            float4 v0 = *(const float4*)&Vs[kk][tx * 4];
            float4 v1 = *(const float4*)&Vs[kk + 1][tx * 4];
#pragma unroll
            for (int i = 0; i < 4; ++i) {
                float2 pf = __half22float2(*(const __half2*)&Ps[ty * 4 + i][kk]);
                acc[i][0] += pf.x * v0.x + pf.y * v1.x;
                acc[i][1] += pf.x * v0.y + pf.y * v1.y;
                acc[i][2] += pf.x * v0.z + pf.y * v1.z;
                acc[i][3] += pf.x * v0.w + pf.y * v1.w;
            }
        }
    }

#pragma unroll
    for (int i = 0; i < 4; ++i) {
        int q = q0 + ty * 4 + i;
        float inv = 1.0f / g_psum[bh * 1024 + q];
        size_t gi = ((size_t)(b * 1024 + q)) * 512 + h * 32 + tx * 4;
        float4 gv = *(const float4*)&g_g[gi];
        float4 o;
        o.x = acc[i][0] * inv * gv.x;
        o.y = acc[i][1] * inv * gv.y;
        o.z = acc[i][2] * inv * gv.z;
        o.w = acc[i][3] * inv * gv.w;
        *(float4*)&g_og[gi] = o;
    }
}

// ---------------- kernel 4: out = og @ w_o + b_o ----------------
__global__ __launch_bounds__(256) void out_kernel(const float* __restrict__ wo,
                                                  const float* __restrict__ bo,
                                                  float* __restrict__ out) {
    __shared__ float As[16][68];
    __shared__ float Bs[16][68];
    int bx = blockIdx.x;
    int by = blockIdx.y;
    int tid = threadIdx.x;
    int tx = tid & 15, ty = tid >> 4;
    int cl0 = bx * 64;
    float acc[4][4] = {};
    int aRow = tid >> 2, aK4 = (tid & 3) * 4;
    int bK = tid >> 4, bC4 = (tid & 15) * 4;
    for (int k0 = 0; k0 < 512; k0 += 16) {
        float4 va = *(const float4*)(g_og + (size_t)(by * 64 + aRow) * 512 + k0 + aK4);
        float4 vb = *(const float4*)(wo + (size_t)(k0 + bK) * 512 + cl0 + bC4);
        __syncthreads();
        As[aK4 + 0][aRow] = va.x;
        As[aK4 + 1][aRow] = va.y;
        As[aK4 + 2][aRow] = va.z;
        As[aK4 + 3][aRow] = va.w;
        *(float4*)&Bs[bK][bC4] = vb;
        __syncthreads();
#pragma unroll
        for (int kk = 0; kk < 16; ++kk) {
            float4 a = *(const float4*)&As[kk][ty * 4];
            float4 b = *(const float4*)&Bs[kk][tx * 4];
            float ar[4] = {a.x, a.y, a.z, a.w};
            float br[4] = {b.x, b.y, b.z, b.w};
#pragma unroll
            for (int i = 0; i < 4; ++i)
#pragma unroll
                for (int j = 0; j < 4; ++j) acc[i][j] += ar[i] * br[j];
        }
    }
#pragma unroll
    for (int i = 0; i < 4; ++i) {
        int row = by * 64 + ty * 4 + i;
#pragma unroll
        for (int j = 0; j < 4; ++j) {
            int col = cl0 + tx * 4 + j;
            out[(size_t)row * 512 + col] = acc[i][j] + bo[col];
        }
    }
}

// ---------------- launch ----------------
extern "C" void kernel_launch(void* const* d_in, const int* in_sizes, int n_in,
                              void* d_out, int out_size) {
    const float* m      = (const float*)d_in[0];
    const float* z      = (const float*)d_in[1];
    const float* mask   = (const float*)d_in[2];
    const float* ln_m_w = (const float*)d_in[3];
    const float* ln_m_b = (const float*)d_in[4];
    const float* ln_z_w = (const float*)d_in[5];
    const float* ln_z_b = (const float*)d_in[6];
    const float* w_z    = (const float*)d_in[7];
    const float* w_q    = (const float*)d_in[8];
    const float* w_k    = (const float*)d_in[9];
    const float* w_v    = (const float*)d_in[10];
    const float* w_g    = (const float*)d_in[11];
    const float* b_g    = (const float*)d_in[12];
    const float* w_o    = (const float*)d_in[13];
    const float* b_o    = (const float*)d_in[14];
    float* out = (float*)d_out;

    const int smem_bias = (16384 + 1056 + 32) * 4;   // 69,888 B
    cudaFuncSetAttribute(bias_attn_kernel,
                         cudaFuncAttributeMaxDynamicSharedMemorySize, smem_bias);

    ln_m_kernel<<<BB * NN, 128>>>(m, ln_m_w, ln_m_b);
    proj_kernel<<<dim3(32, 32), 256>>>(w_q, w_k, w_v, w_g, b_g);
    qk_kernel<<<dim3(64, 32), 512>>>();
    bias_attn_kernel<<<BB * NN, 512, smem_bias>>>(z, mask, ln_z_w, ln_z_b, w_z);
    av_kernel<<<dim3(8, 32), 256>>>();
    out_kernel<<<dim3(8, 32), 256>>>(w_o, b_o, out);
}

// round 16
// speedup vs baseline: 3.4838x; 1.5331x over previous
#include <cuda_runtime.h>
#include <cuda_fp16.h>
#include <cstdint>
#include <math.h>

#define BB 2
#define NN 1024
#define CIN 512
#define HH 16
#define DH 32
#define CZ 128

// ---------------- scratch (device globals; no allocation) ----------------
__device__ float g_mln[BB * NN * CIN];
__device__ float g_q[BB * NN * CIN];
__device__ float g_k[BB * NN * CIN];
__device__ float g_v[BB * NN * CIN];
__device__ float g_g[BB * NN * CIN];
__device__ float g_og[BB * NN * CIN];
__device__ float g_qk[(size_t)BB * HH * NN * NN];       // QK^T logits fp32 (128MB)
__device__ __half g_probs[(size_t)BB * HH * NN * NN];   // unnormalized exp fp16 (64MB)
__device__ float g_psum[BB * HH * NN];                  // softmax row sums

__device__ __forceinline__ void cp_async16(unsigned int saddr, const void* gptr) {
    asm volatile("cp.async.cg.shared.global [%0], [%1], 16;" :: "r"(saddr), "l"(gptr));
}
__device__ __forceinline__ void cp_commit() {
    asm volatile("cp.async.commit_group;" ::: "memory");
}
template <int N>
__device__ __forceinline__ void cp_wait() {
    asm volatile("cp.async.wait_group %0;" :: "n"(N) : "memory");
}

// ---------------- kernel 1a: LayerNorm(m) ----------------
__global__ __launch_bounds__(128) void ln_m_kernel(const float* __restrict__ m,
                                                   const float* __restrict__ w,
                                                   const float* __restrict__ b) {
    int row = blockIdx.x;
    int tid = threadIdx.x;
    const float4* mp = (const float4*)m + (size_t)row * 128;
    float4 x = mp[tid];
    float s = x.x + x.y + x.z + x.w;
    float q2 = x.x * x.x + x.y * x.y + x.z * x.z + x.w * x.w;
#pragma unroll
    for (int o = 16; o; o >>= 1) {
        s  += __shfl_xor_sync(0xffffffffu, s, o);
        q2 += __shfl_xor_sync(0xffffffffu, q2, o);
    }
    __shared__ float sS[4], sQ[4];
    __shared__ float s_mu, s_rstd;
    int wid = tid >> 5, lane = tid & 31;
    if (lane == 0) { sS[wid] = s; sQ[wid] = q2; }
    __syncthreads();
    if (tid == 0) {
        float ts = sS[0] + sS[1] + sS[2] + sS[3];
        float tq = sQ[0] + sQ[1] + sQ[2] + sQ[3];
        float mu = ts * (1.0f / 512.0f);
        float var = tq * (1.0f / 512.0f) - mu * mu;
        s_mu = mu;
        s_rstd = rsqrtf(var + 1e-5f);
    }
    __syncthreads();
    float mu = s_mu, rstd = s_rstd;
    float4 w4 = ((const float4*)w)[tid];
    float4 b4 = ((const float4*)b)[tid];
    float4 o;
    o.x = (x.x - mu) * rstd * w4.x + b4.x;
    o.y = (x.y - mu) * rstd * w4.y + b4.y;
    o.z = (x.z - mu) * rstd * w4.z + b4.z;
    o.w = (x.w - mu) * rstd * w4.w + b4.w;
    ((float4*)g_mln)[(size_t)row * 128 + tid] = o;
}

// ---------------- kernel 1b: projections q,k,v,g ----------------
__global__ __launch_bounds__(256) void proj_kernel(const float* __restrict__ wq,
                                                   const float* __restrict__ wk,
                                                   const float* __restrict__ wv,
                                                   const float* __restrict__ wg,
                                                   const float* __restrict__ bg) {
    __shared__ float As[16][68];
    __shared__ float Bs[16][68];
    int bx = blockIdx.x;
    int by = blockIdx.y;
    int tid = threadIdx.x;
    int tx = tid & 15, ty = tid >> 4;
    int sel = bx >> 3;
    int cl0 = (bx & 7) * 64;
    const float* W = (sel == 0) ? wq : (sel == 1) ? wk : (sel == 2) ? wv : wg;
    float acc[4][4] = {};
    int aRow = tid >> 2, aK4 = (tid & 3) * 4;
    int bK = tid >> 4, bC4 = (tid & 15) * 4;
    for (int k0 = 0; k0 < 512; k0 += 16) {
        float4 va = *(const float4*)(g_mln + (size_t)(by * 64 + aRow) * 512 + k0 + aK4);
        float4 vb = *(const float4*)(W + (size_t)(k0 + bK) * 512 + cl0 + bC4);
        __syncthreads();
        As[aK4 + 0][aRow] = va.x;
        As[aK4 + 1][aRow] = va.y;
        As[aK4 + 2][aRow] = va.z;
        As[aK4 + 3][aRow] = va.w;
        *(float4*)&Bs[bK][bC4] = vb;
        __syncthreads();
#pragma unroll
        for (int kk = 0; kk < 16; ++kk) {
            float4 a = *(const float4*)&As[kk][ty * 4];
            float4 b = *(const float4*)&Bs[kk][tx * 4];
            float ar[4] = {a.x, a.y, a.z, a.w};
            float br[4] = {b.x, b.y, b.z, b.w};
#pragma unroll
            for (int i = 0; i < 4; ++i)
#pragma unroll
                for (int j = 0; j < 4; ++j) acc[i][j] += ar[i] * br[j];
        }
    }
    const float qscale = 0.17677669529663687f;
#pragma unroll
    for (int i = 0; i < 4; ++i) {
        int row = by * 64 + ty * 4 + i;
#pragma unroll
        for (int j = 0; j < 4; ++j) {
            int col = cl0 + tx * 4 + j;
            size_t oidx = (size_t)row * 512 + col;
            float v = acc[i][j];
            if (sel == 0)      g_q[oidx] = v * qscale;
            else if (sel == 1) g_k[oidx] = v;
            else if (sel == 2) g_v[oidx] = v;
            else               g_g[oidx] = 1.0f / (1.0f + __expf(-(v + bg[col])));
        }
    }
}

// ---------------- kernel 1c: qk[b,h,q,k] = q . k  (batched GEMM) ----------------
__global__ __launch_bounds__(512) void qk_kernel() {
    __shared__ float Qs[128][36];
    __shared__ float Ks[128][36];
    int tid = threadIdx.x;
    int bh = blockIdx.y;
    int b = bh >> 4, h = bh & 15;
    int q0 = (blockIdx.x >> 3) * 128;
    int k0 = (blockIdx.x & 7) * 128;
    const float* qb = g_q + (size_t)(b * 1024) * 512 + h * 32;
    const float* kb = g_k + (size_t)(b * 1024) * 512 + h * 32;
#pragma unroll
    for (int u = 0; u < 2; ++u) {
        int fid = tid + 512 * u;
        int row = fid >> 3, d4 = (fid & 7) * 4;
        *(float4*)&Qs[row][d4] = *(const float4*)(qb + (size_t)(q0 + row) * 512 + d4);
        *(float4*)&Ks[row][d4] = *(const float4*)(kb + (size_t)(k0 + row) * 512 + d4);
    }
    __syncthreads();
    int tx = tid & 15, ty = tid >> 4;
    float acc[4][8] = {};
#pragma unroll
    for (int d4 = 0; d4 < 8; ++d4) {
        float4 av[4], bv[8];
#pragma unroll
        for (int i = 0; i < 4; ++i) av[i] = *(const float4*)&Qs[ty + 32 * i][d4 * 4];
#pragma unroll
        for (int j = 0; j < 8; ++j) bv[j] = *(const float4*)&Ks[tx + 16 * j][d4 * 4];
#pragma unroll
        for (int i = 0; i < 4; ++i)
#pragma unroll
            for (int j = 0; j < 8; ++j)
                acc[i][j] += av[i].x * bv[j].x + av[i].y * bv[j].y +
                             av[i].z * bv[j].z + av[i].w * bv[j].w;
    }
    float* ob = g_qk + ((size_t)bh * 1024 + q0) * 1024 + k0;
#pragma unroll
    for (int i = 0; i < 4; ++i)
#pragma unroll
        for (int j = 0; j < 8; ++j)
            ob[(size_t)(ty + 32 * i) * 1024 + tx + 16 * j] = acc[i][j];
}

// ---------------- kernel 2: fused pair-bias + (+qk) + softmax -> fp16 probs ----------------
// Thread owns rows tid and tid+512 (no shuffles). z staged via cp.async in 8-col tiles.
// dyn smem floats: S[16384] | Zb0[12288] | Zb1[12288] | wzw2[1024 half2 = 1024 f] | s1[16] | c0[16]
#define ZSTRIDE 12
#define ZBUF (1024 * ZSTRIDE)
__global__ __launch_bounds__(512, 1) void bias_attn_kernel(const float* __restrict__ z,
                                                           const float* __restrict__ mask,
                                                           const float* __restrict__ lzw,
                                                           const float* __restrict__ lzb,
                                                           const float* __restrict__ wz) {
    extern __shared__ float smbuf[];
    float* S = smbuf;                                        // 16 x 1024
    float* Zb0 = smbuf + 16384;
    float* Zb1 = Zb0 + ZBUF;
    __half2* wzw2 = (__half2*)(Zb1 + ZBUF);                  // [c][p]: head-pair weights
    float* s1 = (float*)(wzw2 + 1024);
    float* c0 = s1 + 16;

    int tid = threadIdx.x;
    int bq = blockIdx.x;
    int b = bq >> 10, q = bq & 1023;

    // prologue: wzw2[c*8+p] = (lzw[c]*wz[c][2p], lzw[c]*wz[c][2p+1])
    for (int idx = tid; idx < 1024; idx += 512) {
        int c = idx >> 3, p = idx & 7;
        float lw = lzw[c];
        wzw2[idx] = __floats2half2_rn(lw * wz[c * 16 + 2 * p],
                                      lw * wz[c * 16 + 2 * p + 1]);
    }
    if (tid < 16) {
        float a = 0.f, bb2 = 0.f;
#pragma unroll 4
        for (int c = 0; c < 128; ++c) {
            a   += lzw[c] * wz[c * 16 + tid];
            bb2 += lzb[c] * wz[c * 16 + tid];
        }
        s1[tid] = a;
        c0[tid] = bb2;
    }

    const float* zrow = z + (size_t)bq * 1024 * 128;   // this (b,q)'s z[k][c] slab
    unsigned int zs0 = (unsigned int)__cvta_generic_to_shared(Zb0);
    unsigned int zs1 = (unsigned int)__cvta_generic_to_shared(Zb1);

    // prefetch tiles 0, 1 (each: 1024 rows x 8 c; thread loads 4 x 16B coalesced)
#pragma unroll
    for (int t0 = 0; t0 < 2; ++t0) {
        unsigned int dstb = t0 ? zs1 : zs0;
#pragma unroll
        for (int u = 0; u < 4; ++u) {
            int i = tid + 512 * u;
            int row = i >> 1, half = i & 1;
            cp_async16(dstb + (row * ZSTRIDE + half * 4) * 4,
                       zrow + (size_t)row * 128 + t0 * 8 + half * 4);
        }
        cp_commit();
    }

    int k0r = tid, k1r = tid + 512;
    float d0[16], d1[16];
#pragma unroll
    for (int hh = 0; hh < 16; ++hh) { d0[hh] = 0.f; d1[hh] = 0.f; }
    float sm0 = 0.f, sq0 = 0.f, sm1 = 0.f, sq1 = 0.f;
    const __half2 hz = __float2half2_rn(0.f);

#pragma unroll 1
    for (int ct = 0; ct < 16; ++ct) {
        if (ct == 15) cp_wait<0>(); else cp_wait<1>();
        __syncthreads();                       // tile ct visible (also covers prologue at ct=0)

        const float* Z = (ct & 1) ? Zb1 : Zb0;
        float4 xa0 = *(const float4*)(Z + k0r * ZSTRIDE);
        float4 xa1 = *(const float4*)(Z + k0r * ZSTRIDE + 4);
        float4 xb0 = *(const float4*)(Z + k1r * ZSTRIDE);
        float4 xb1 = *(const float4*)(Z + k1r * ZSTRIDE + 4);

        __half2 a0[8], a1[8];
#pragma unroll
        for (int p = 0; p < 8; ++p) { a0[p] = hz; a1[p] = hz; }

#pragma unroll
        for (int jj = 0; jj < 8; ++jj) {
            float x0 = (jj < 4) ? ((jj == 0) ? xa0.x : (jj == 1) ? xa0.y : (jj == 2) ? xa0.z : xa0.w)
                                : ((jj == 4) ? xa1.x : (jj == 5) ? xa1.y : (jj == 6) ? xa1.z : xa1.w);
            float x1 = (jj < 4) ? ((jj == 0) ? xb0.x : (jj == 1) ? xb0.y : (jj == 2) ? xb0.z : xb0.w)
                                : ((jj == 4) ? xb1.x : (jj == 5) ? xb1.y : (jj == 6) ? xb1.z : xb1.w);
            sm0 += x0; sq0 += x0 * x0;
            sm1 += x1; sq1 += x1 * x1;
            __half2 xh0 = __float2half2_rn(x0);
            __half2 xh1 = __float2half2_rn(x1);
            const float4* wr = (const float4*)(wzw2 + (size_t)(ct * 8 + jj) * 8);  // uniform -> broadcast
            float4 wA = wr[0];
            float4 wB = wr[1];
            const __half2* wpa = (const __half2*)&wA;
            const __half2* wpb = (const __half2*)&wB;
            a0[0] = __hfma2(xh0, wpa[0], a0[0]);
            a0[1] = __hfma2(xh0, wpa[1], a0[1]);
            a0[2] = __hfma2(xh0, wpa[2], a0[2]);
            a0[3] = __hfma2(xh0, wpa[3], a0[3]);
            a0[4] = __hfma2(xh0, wpb[0], a0[4]);
            a0[5] = __hfma2(xh0, wpb[1], a0[5]);
            a0[6] = __hfma2(xh0, wpb[2], a0[6]);
            a0[7] = __hfma2(xh0, wpb[3], a0[7]);
            a1[0] = __hfma2(xh1, wpa[0], a1[0]);
            a1[1] = __hfma2(xh1, wpa[1], a1[1]);
            a1[2] = __hfma2(xh1, wpa[2], a1[2]);
            a1[3] = __hfma2(xh1, wpa[3], a1[3]);
            a1[4] = __hfma2(xh1, wpb[0], a1[4]);
            a1[5] = __hfma2(xh1, wpb[1], a1[5]);
            a1[6] = __hfma2(xh1, wpb[2], a1[6]);
            a1[7] = __hfma2(xh1, wpb[3], a1[7]);
        }

        // flush fp16 tile-partials -> fp32
#pragma unroll
        for (int p = 0; p < 8; ++p) {
            float2 f0 = __half22float2(a0[p]);
            float2 f1 = __half22float2(a1[p]);
            d0[2 * p]     += f0.x;
            d0[2 * p + 1] += f0.y;
            d1[2 * p]     += f1.x;
            d1[2 * p + 1] += f1.y;
        }

        __syncthreads();                       // done reading buf (ct&1) before overwrite
        if (ct + 2 < 16) {
            unsigned int dstb = (ct & 1) ? zs1 : zs0;   // (ct+2)&1 == ct&1
#pragma unroll
            for (int u = 0; u < 4; ++u) {
                int i = tid + 512 * u;
                int row = i >> 1, half = i & 1;
                cp_async16(dstb + (row * ZSTRIDE + half * 4) * 4,
                           zrow + (size_t)row * 128 + (ct + 2) * 8 + half * 4);
            }
            cp_commit();
        }
    }

    {   // epilogue: LN combine, write bias rows to smem
        float mu0 = sm0 * (1.0f / 128.0f);
        float rstd0 = rsqrtf(sq0 * (1.0f / 128.0f) - mu0 * mu0 + 1e-5f);
        float mb0 = 1e9f * (mask[b * 1024 + k0r] - 1.0f);
        float mu1 = sm1 * (1.0f / 128.0f);
        float rstd1 = rsqrtf(sq1 * (1.0f / 128.0f) - mu1 * mu1 + 1e-5f);
        float mb1 = 1e9f * (mask[b * 1024 + k1r] - 1.0f);
#pragma unroll
        for (int h = 0; h < 16; ++h) {
            float s1h = s1[h], c0h = c0[h];
            S[h * 1024 + k0r] = rstd0 * (d0[h] - mu0 * s1h) + c0h + mb0;
            S[h * 1024 + k1r] = rstd1 * (d1[h] - mu1 * s1h) + c0h + mb1;
        }
    }
    __syncthreads();

    // ---- phase B: warp w owns head w: add qk logits, softmax, fp16 probs ----
    {
        int h = tid >> 5, lane = tid & 31;
        const float4* qkr = (const float4*)(g_qk + (((size_t)(b * 16 + h)) * 1024 + q) * 1024);
        float4 sv[8];
        float mx = -1e30f;
#pragma unroll
        for (int i = 0; i < 8; ++i) {
            float4 s = *(const float4*)&S[h * 1024 + lane * 4 + i * 128];
            float4 qk = qkr[lane + i * 32];
            s.x += qk.x; s.y += qk.y; s.z += qk.z; s.w += qk.w;
            sv[i] = s;
            mx = fmaxf(mx, fmaxf(fmaxf(s.x, s.y), fmaxf(s.z, s.w)));
        }
#pragma unroll
        for (int o = 16; o; o >>= 1) mx = fmaxf(mx, __shfl_xor_sync(0xffffffffu, mx, o));

        __half* prow = g_probs + (((size_t)(b * 16 + h)) * 1024 + q) * 1024;
        float sum = 0.f;
#pragma unroll
        for (int i = 0; i < 8; ++i) {
            float e0 = __expf(sv[i].x - mx);
            float e1 = __expf(sv[i].y - mx);
            float e2 = __expf(sv[i].z - mx);
            float e3 = __expf(sv[i].w - mx);
            sum += (e0 + e1) + (e2 + e3);
            __half2 p0 = __floats2half2_rn(e0, e1);
            __half2 p1 = __floats2half2_rn(e2, e3);
            uint2 pk;
            pk.x = reinterpret_cast<unsigned int&>(p0);
            pk.y = reinterpret_cast<unsigned int&>(p1);
            *(uint2*)(prow + lane * 4 + i * 128) = pk;
        }
#pragma unroll
        for (int o = 16; o; o >>= 1) sum += __shfl_xor_sync(0xffffffffu, sum, o);
        if (lane == 0) g_psum[(b * 16 + h) * 1024 + q] = sum;
    }
}

// ---------------- kernel 3: AV + gate ----------------
__global__ __launch_bounds__(256) void av_kernel() {
    __shared__ __half Ps[128][72];
    __shared__ float  Vs[64][36];
    int tid = threadIdx.x;
    int tx = tid & 7;
    int ty = tid >> 3;
    int bh = blockIdx.y;
    int b = bh >> 4, h = bh & 15;
    int q0 = blockIdx.x * 128;

    const __half* pb = g_probs + ((size_t)bh * 1024 + q0) * 1024;
    const float* vb = g_v + (size_t)b * 1024 * 512 + h * 32;

    float acc[4][4] = {};

    for (int kt = 0; kt < 16; ++kt) {
        __syncthreads();
#pragma unroll
        for (int u = 0; u < 4; ++u) {
            int id = tid + 256 * u;
            int row = id >> 3, c8 = id & 7;
            *(uint4*)&Ps[row][c8 * 8] = *(const uint4*)(pb + (size_t)row * 1024 + kt * 64 + c8 * 8);
        }
#pragma unroll
        for (int u = 0; u < 2; ++u) {
            int id = tid + 256 * u;
            int row = id >> 3, d4 = id & 7;
            *(float4*)&Vs[row][d4 * 4] = *(const float4*)(vb + (size_t)(kt * 64 + row) * 512 + d4 * 4);
        }
        __syncthreads();
#pragma unroll 4
        for (int k2 = 0; k2 < 32; ++k2) {
            int kk = k2 * 2;
            float4 v0 = *(const float4*)&Vs[kk][tx * 4];
            float4 v1 = *(const float4*)&Vs[kk + 1][tx * 4];
#pragma unroll
            for (int i = 0; i < 4; ++i) {
                float2 pf = __half22float2(*(const __half2*)&Ps[ty * 4 + i][kk]);
                acc[i][0] += pf.x * v0.x + pf.y * v1.x;
                acc[i][1] += pf.x * v0.y + pf.y * v1.y;
                acc[i][2] += pf.x * v0.z + pf.y * v1.z;
                acc[i][3] += pf.x * v0.w + pf.y * v1.w;
            }
        }
    }

#pragma unroll
    for (int i = 0; i < 4; ++i) {
        int q = q0 + ty * 4 + i;
        float inv = 1.0f / g_psum[bh * 1024 + q];
        size_t gi = ((size_t)(b * 1024 + q)) * 512 + h * 32 + tx * 4;
        float4 gv = *(const float4*)&g_g[gi];
        float4 o;
        o.x = acc[i][0] * inv * gv.x;
        o.y = acc[i][1] * inv * gv.y;
        o.z = acc[i][2] * inv * gv.z;
        o.w = acc[i][3] * inv * gv.w;
        *(float4*)&g_og[gi] = o;
    }
}

// ---------------- kernel 4: out = og @ w_o + b_o ----------------
__global__ __launch_bounds__(256) void out_kernel(const float* __restrict__ wo,
                                                  const float* __restrict__ bo,
                                                  float* __restrict__ out) {
    __shared__ float As[16][68];
    __shared__ float Bs[16][68];
    int bx = blockIdx.x;
    int by = blockIdx.y;
    int tid = threadIdx.x;
    int tx = tid & 15, ty = tid >> 4;
    int cl0 = bx * 64;
    float acc[4][4] = {};
    int aRow = tid >> 2, aK4 = (tid & 3) * 4;
    int bK = tid >> 4, bC4 = (tid & 15) * 4;
    for (int k0 = 0; k0 < 512; k0 += 16) {
        float4 va = *(const float4*)(g_og + (size_t)(by * 64 + aRow) * 512 + k0 + aK4);
        float4 vb = *(const float4*)(wo + (size_t)(k0 + bK) * 512 + cl0 + bC4);
        __syncthreads();
        As[aK4 + 0][aRow] = va.x;
        As[aK4 + 1][aRow] = va.y;
        As[aK4 + 2][aRow] = va.z;
        As[aK4 + 3][aRow] = va.w;
        *(float4*)&Bs[bK][bC4] = vb;
        __syncthreads();
#pragma unroll
        for (int kk = 0; kk < 16; ++kk) {
            float4 a = *(const float4*)&As[kk][ty * 4];
            float4 b = *(const float4*)&Bs[kk][tx * 4];
            float ar[4] = {a.x, a.y, a.z, a.w};
            float br[4] = {b.x, b.y, b.z, b.w};
#pragma unroll
            for (int i = 0; i < 4; ++i)
#pragma unroll
                for (int j = 0; j < 4; ++j) acc[i][j] += ar[i] * br[j];
        }
    }
#pragma unroll
    for (int i = 0; i < 4; ++i) {
        int row = by * 64 + ty * 4 + i;
#pragma unroll
        for (int j = 0; j < 4; ++j) {
            int col = cl0 + tx * 4 + j;
            out[(size_t)row * 512 + col] = acc[i][j] + bo[col];
        }
    }
}

// ---------------- launch ----------------
extern "C" void kernel_launch(void* const* d_in, const int* in_sizes, int n_in,
                              void* d_out, int out_size) {
    const float* m      = (const float*)d_in[0];
    const float* z      = (const float*)d_in[1];
    const float* mask   = (const float*)d_in[2];
    const float* ln_m_w = (const float*)d_in[3];
    const float* ln_m_b = (const float*)d_in[4];
    const float* ln_z_w = (const float*)d_in[5];
    const float* ln_z_b = (const float*)d_in[6];
    const float* w_z    = (const float*)d_in[7];
    const float* w_q    = (const float*)d_in[8];
    const float* w_k    = (const float*)d_in[9];
    const float* w_v    = (const float*)d_in[10];
    const float* w_g    = (const float*)d_in[11];
    const float* b_g    = (const float*)d_in[12];
    const float* w_o    = (const float*)d_in[13];
    const float* b_o    = (const float*)d_in[14];
    float* out = (float*)d_out;

    const int smem_bias = (16384 + 2 * ZBUF + 1024 + 32) * 4;   // 167,936 B
    cudaFuncSetAttribute(bias_attn_kernel,
                         cudaFuncAttributeMaxDynamicSharedMemorySize, smem_bias);

    ln_m_kernel<<<BB * NN, 128>>>(m, ln_m_w, ln_m_b);
    proj_kernel<<<dim3(32, 32), 256>>>(w_q, w_k, w_v, w_g, b_g);
    qk_kernel<<<dim3(64, 32), 512>>>();
    bias_attn_kernel<<<BB * NN, 512, smem_bias>>>(z, mask, ln_z_w, ln_z_b, w_z);
    av_kernel<<<dim3(8, 32), 256>>>();
    out_kernel<<<dim3(8, 32), 256>>>(w_o, b_o, out);
}

// round 17
// speedup vs baseline: 3.7802x; 1.0851x over previous
#include <cuda_runtime.h>
#include <cuda_fp16.h>
#include <cstdint>
#include <math.h>

#define BB 2
#define NN 1024
#define CIN 512
#define HH 16
#define DH 32
#define CZ 128

// ---------------- scratch (device globals; no allocation) ----------------
__device__ float g_mln[BB * NN * CIN];
__device__ float g_q[BB * NN * CIN];
__device__ float g_k[BB * NN * CIN];
__device__ float g_v[BB * NN * CIN];
__device__ float g_g[BB * NN * CIN];
__device__ float g_og[BB * NN * CIN];
__device__ float g_qk[(size_t)BB * HH * NN * NN];       // QK^T logits fp32 (128MB)
__device__ __half g_probs[(size_t)BB * HH * NN * NN];   // unnormalized exp fp16 (64MB)
__device__ float g_psum[BB * HH * NN];                  // softmax row sums

__device__ __forceinline__ void cp_async16(unsigned int saddr, const void* gptr) {
    asm volatile("cp.async.cg.shared.global [%0], [%1], 16;" :: "r"(saddr), "l"(gptr));
}
__device__ __forceinline__ void cp_commit() {
    asm volatile("cp.async.commit_group;" ::: "memory");
}
template <int N>
__device__ __forceinline__ void cp_wait() {
    asm volatile("cp.async.wait_group %0;" :: "n"(N) : "memory");
}

// ---------------- kernel 1a: LayerNorm(m) ----------------
__global__ __launch_bounds__(128) void ln_m_kernel(const float* __restrict__ m,
                                                   const float* __restrict__ w,
                                                   const float* __restrict__ b) {
    int row = blockIdx.x;
    int tid = threadIdx.x;
    const float4* mp = (const float4*)m + (size_t)row * 128;
    float4 x = mp[tid];
    float s = x.x + x.y + x.z + x.w;
    float q2 = x.x * x.x + x.y * x.y + x.z * x.z + x.w * x.w;
#pragma unroll
    for (int o = 16; o; o >>= 1) {
        s  += __shfl_xor_sync(0xffffffffu, s, o);
        q2 += __shfl_xor_sync(0xffffffffu, q2, o);
    }
    __shared__ float sS[4], sQ[4];
    __shared__ float s_mu, s_rstd;
    int wid = tid >> 5, lane = tid & 31;
    if (lane == 0) { sS[wid] = s; sQ[wid] = q2; }
    __syncthreads();
    if (tid == 0) {
        float ts = sS[0] + sS[1] + sS[2] + sS[3];
        float tq = sQ[0] + sQ[1] + sQ[2] + sQ[3];
        float mu = ts * (1.0f / 512.0f);
        float var = tq * (1.0f / 512.0f) - mu * mu;
        s_mu = mu;
        s_rstd = rsqrtf(var + 1e-5f);
    }
    __syncthreads();
    float mu = s_mu, rstd = s_rstd;
    float4 w4 = ((const float4*)w)[tid];
    float4 b4 = ((const float4*)b)[tid];
    float4 o;
    o.x = (x.x - mu) * rstd * w4.x + b4.x;
    o.y = (x.y - mu) * rstd * w4.y + b4.y;
    o.z = (x.z - mu) * rstd * w4.z + b4.z;
    o.w = (x.w - mu) * rstd * w4.w + b4.w;
    ((float4*)g_mln)[(size_t)row * 128 + tid] = o;
}

// ---------------- kernel 1b: projections q,k,v,g ----------------
__global__ __launch_bounds__(256) void proj_kernel(const float* __restrict__ wq,
                                                   const float* __restrict__ wk,
                                                   const float* __restrict__ wv,
                                                   const float* __restrict__ wg,
                                                   const float* __restrict__ bg) {
    __shared__ float As[16][68];
    __shared__ float Bs[16][68];
    int bx = blockIdx.x;
    int by = blockIdx.y;
    int tid = threadIdx.x;
    int tx = tid & 15, ty = tid >> 4;
    int sel = bx >> 3;
    int cl0 = (bx & 7) * 64;
    const float* W = (sel == 0) ? wq : (sel == 1) ? wk : (sel == 2) ? wv : wg;
    float acc[4][4] = {};
    int aRow = tid >> 2, aK4 = (tid & 3) * 4;
    int bK = tid >> 4, bC4 = (tid & 15) * 4;
    for (int k0 = 0; k0 < 512; k0 += 16) {
        float4 va = *(const float4*)(g_mln + (size_t)(by * 64 + aRow) * 512 + k0 + aK4);
        float4 vb = *(const float4*)(W + (size_t)(k0 + bK) * 512 + cl0 + bC4);
        __syncthreads();
        As[aK4 + 0][aRow] = va.x;
        As[aK4 + 1][aRow] = va.y;
        As[aK4 + 2][aRow] = va.z;
        As[aK4 + 3][aRow] = va.w;
        *(float4*)&Bs[bK][bC4] = vb;
        __syncthreads();
#pragma unroll
        for (int kk = 0; kk < 16; ++kk) {
            float4 a = *(const float4*)&As[kk][ty * 4];
            float4 b = *(const float4*)&Bs[kk][tx * 4];
            float ar[4] = {a.x, a.y, a.z, a.w};
            float br[4] = {b.x, b.y, b.z, b.w};
#pragma unroll
            for (int i = 0; i < 4; ++i)
#pragma unroll
                for (int j = 0; j < 4; ++j) acc[i][j] += ar[i] * br[j];
        }
    }
    const float qscale = 0.17677669529663687f;
#pragma unroll
    for (int i = 0; i < 4; ++i) {
        int row = by * 64 + ty * 4 + i;
#pragma unroll
        for (int j = 0; j < 4; ++j) {
            int col = cl0 + tx * 4 + j;
            size_t oidx = (size_t)row * 512 + col;
            float v = acc[i][j];
            if (sel == 0)      g_q[oidx] = v * qscale;
            else if (sel == 1) g_k[oidx] = v;
            else if (sel == 2) g_v[oidx] = v;
            else               g_g[oidx] = 1.0f / (1.0f + __expf(-(v + bg[col])));
        }
    }
}

// ---------------- kernel 1c: qk[b,h,q,k] = q . k  (batched GEMM) ----------------
__global__ __launch_bounds__(512) void qk_kernel() {
    __shared__ float Qs[128][36];
    __shared__ float Ks[128][36];
    int tid = threadIdx.x;
    int bh = blockIdx.y;
    int b = bh >> 4, h = bh & 15;
    int q0 = (blockIdx.x >> 3) * 128;
    int k0 = (blockIdx.x & 7) * 128;
    const float* qb = g_q + (size_t)(b * 1024) * 512 + h * 32;
    const float* kb = g_k + (size_t)(b * 1024) * 512 + h * 32;
#pragma unroll
    for (int u = 0; u < 2; ++u) {
        int fid = tid + 512 * u;
        int row = fid >> 3, d4 = (fid & 7) * 4;
        *(float4*)&Qs[row][d4] = *(const float4*)(qb + (size_t)(q0 + row) * 512 + d4);
        *(float4*)&Ks[row][d4] = *(const float4*)(kb + (size_t)(k0 + row) * 512 + d4);
    }
    __syncthreads();
    int tx = tid & 15, ty = tid >> 4;
    float acc[4][8] = {};
#pragma unroll
    for (int d4 = 0; d4 < 8; ++d4) {
        float4 av[4], bv[8];
#pragma unroll
        for (int i = 0; i < 4; ++i) av[i] = *(const float4*)&Qs[ty + 32 * i][d4 * 4];
#pragma unroll
        for (int j = 0; j < 8; ++j) bv[j] = *(const float4*)&Ks[tx + 16 * j][d4 * 4];
#pragma unroll
        for (int i = 0; i < 4; ++i)
#pragma unroll
            for (int j = 0; j < 8; ++j)
                acc[i][j] += av[i].x * bv[j].x + av[i].y * bv[j].y +
                             av[i].z * bv[j].z + av[i].w * bv[j].w;
    }
    float* ob = g_qk + ((size_t)bh * 1024 + q0) * 1024 + k0;
#pragma unroll
    for (int i = 0; i < 4; ++i)
#pragma unroll
        for (int j = 0; j < 8; ++j)
            ob[(size_t)(ty + 32 * i) * 1024 + tx + 16 * j] = acc[i][j];
}

// ---------------- kernel 2: fused pair-bias + (+qk) + softmax -> fp16 probs ----------------
// 2 CTAs/SM. S stored fp16 (mask bias applied in phase B). z staged in 512-row x 8-col tiles.
// smem floats: S16(8192) | Zb0(6144) | Zb1(6144) | wzw2(1024) | s1(16) | c0(16) | mbias(1024)
#define ZST 12
#define ZBUFW (512 * ZST)
__global__ __launch_bounds__(512, 2) void bias_attn_kernel(const float* __restrict__ z,
                                                           const float* __restrict__ mask,
                                                           const float* __restrict__ lzw,
                                                           const float* __restrict__ lzb,
                                                           const float* __restrict__ wz) {
    extern __shared__ float smbuf[];
    __half* S16 = (__half*)smbuf;                       // 16 x 1024 halves (32KB)
    float* Zb0 = smbuf + 8192;
    float* Zb1 = Zb0 + ZBUFW;
    __half2* wzw2 = (__half2*)(Zb1 + ZBUFW);            // [c][p] head-pair weights
    float* s1 = (float*)(wzw2 + 1024);
    float* c0 = s1 + 16;
    float* mbias = c0 + 16;                             // 1024 floats

    int tid = threadIdx.x;
    int bq = blockIdx.x;
    int b = bq >> 10, q = bq & 1023;

    // prologue: weights + mask bias
    for (int idx = tid; idx < 1024; idx += 512) {
        int c = idx >> 3, p = idx & 7;
        float lw = lzw[c];
        wzw2[idx] = __floats2half2_rn(lw * wz[c * 16 + 2 * p],
                                      lw * wz[c * 16 + 2 * p + 1]);
        mbias[idx] = 1e9f * (mask[b * 1024 + idx] - 1.0f);
    }
    if (tid < 16) {
        float a = 0.f, bb2 = 0.f;
#pragma unroll 4
        for (int c = 0; c < 128; ++c) {
            a   += lzw[c] * wz[c * 16 + tid];
            bb2 += lzb[c] * wz[c * 16 + tid];
        }
        s1[tid] = a;
        c0[tid] = bb2;
    }

    const float* zrow = z + (size_t)bq * 1024 * 128;
    unsigned int zs0 = (unsigned int)__cvta_generic_to_shared(Zb0);
    unsigned int zs1 = (unsigned int)__cvta_generic_to_shared(Zb1);

    // prefetch tiles 0, 1 (tile t: rows (t>>4)*512 .. +512, cols (t&15)*8 .. +8)
#pragma unroll
    for (int t0 = 0; t0 < 2; ++t0) {
        unsigned int dstb = t0 ? zs1 : zs0;
        int rowbase = (t0 >> 4) * 512;
        int c8 = (t0 & 15) * 8;
#pragma unroll
        for (int u = 0; u < 2; ++u) {
            int cid = tid + 512 * u;
            int row = cid >> 1, hf = cid & 1;
            cp_async16(dstb + (row * ZST + hf * 4) * 4,
                       zrow + (size_t)(rowbase + row) * 128 + c8 + hf * 4);
        }
        cp_commit();
    }

    const __half2 hz = __float2half2_rn(0.f);
    float d[16];
    float sm = 0.f, sq = 0.f;

#pragma unroll 1
    for (int t = 0; t < 32; ++t) {
        int j8 = t & 15;
        if (j8 == 0) {
#pragma unroll
            for (int hh = 0; hh < 16; ++hh) d[hh] = 0.f;
            sm = 0.f; sq = 0.f;
        }
        if (t == 31) cp_wait<0>(); else cp_wait<1>();
        __syncthreads();                        // tile t visible (covers prologue at t=0)

        const float* Z = (t & 1) ? Zb1 : Zb0;
        float4 x0 = *(const float4*)(Z + tid * ZST);
        float4 x1 = *(const float4*)(Z + tid * ZST + 4);

        __half2 a[8];
#pragma unroll
        for (int p = 0; p < 8; ++p) a[p] = hz;

#pragma unroll
        for (int jj = 0; jj < 8; ++jj) {
            float x = (jj < 4) ? ((jj == 0) ? x0.x : (jj == 1) ? x0.y : (jj == 2) ? x0.z : x0.w)
                               : ((jj == 4) ? x1.x : (jj == 5) ? x1.y : (jj == 6) ? x1.z : x1.w);
            sm += x; sq += x * x;
            __half2 xh = __float2half2_rn(x);
            const float4* wr = (const float4*)(wzw2 + (size_t)(j8 * 8 + jj) * 8);  // uniform broadcast
            float4 wA = wr[0];
            float4 wB = wr[1];
            const __half2* wpa = (const __half2*)&wA;
            const __half2* wpb = (const __half2*)&wB;
            a[0] = __hfma2(xh, wpa[0], a[0]);
            a[1] = __hfma2(xh, wpa[1], a[1]);
            a[2] = __hfma2(xh, wpa[2], a[2]);
            a[3] = __hfma2(xh, wpa[3], a[3]);
            a[4] = __hfma2(xh, wpb[0], a[4]);
            a[5] = __hfma2(xh, wpb[1], a[5]);
            a[6] = __hfma2(xh, wpb[2], a[6]);
            a[7] = __hfma2(xh, wpb[3], a[7]);
        }
#pragma unroll
        for (int p = 0; p < 8; ++p) {
            float2 f = __half22float2(a[p]);
            d[2 * p]     += f.x;
            d[2 * p + 1] += f.y;
        }

        __syncthreads();                        // done reading buf before overwrite
        if (t + 2 < 32) {
            int tn = t + 2;
            unsigned int dstb = (tn & 1) ? zs1 : zs0;
            int rowbase = (tn >> 4) * 512;
            int c8 = (tn & 15) * 8;
#pragma unroll
            for (int u = 0; u < 2; ++u) {
                int cid = tid + 512 * u;
                int row = cid >> 1, hf = cid & 1;
                cp_async16(dstb + (row * ZST + hf * 4) * 4,
                           zrow + (size_t)(rowbase + row) * 128 + c8 + hf * 4);
            }
            cp_commit();
        }

        if (j8 == 15) {                         // epilogue for this half's row
            int k = (t >> 4) * 512 + tid;
            float mu = sm * (1.0f / 128.0f);
            float rstd = rsqrtf(sq * (1.0f / 128.0f) - mu * mu + 1e-5f);
#pragma unroll
            for (int h = 0; h < 16; ++h)
                S16[h * 1024 + k] = __float2half(rstd * (d[h] - mu * s1[h]) + c0[h]);
        }
    }
    __syncthreads();

    // ---- phase B: warp w owns head w: add qk + mask bias, softmax, fp16 probs ----
    {
        int h = tid >> 5, lane = tid & 31;
        const __half* Sh = S16 + h * 1024;
        const float4* qkr = (const float4*)(g_qk + (((size_t)(b * 16 + h)) * 1024 + q) * 1024);
        float4 sv[8];
        float mx = -1e30f;
#pragma unroll
        for (int i = 0; i < 8; ++i) {
            int kk = lane * 4 + i * 128;
            uint2 sraw = *(const uint2*)(Sh + kk);
            __half2 sA = reinterpret_cast<__half2&>(sraw.x);
            __half2 sB = reinterpret_cast<__half2&>(sraw.y);
            float2 f01 = __half22float2(sA);
            float2 f23 = __half22float2(sB);
            float4 qk = qkr[lane + i * 32];
            float4 mb4 = *(const float4*)(mbias + kk);
            float4 s;
            s.x = f01.x + qk.x + mb4.x;
            s.y = f01.y + qk.y + mb4.y;
            s.z = f23.x + qk.z + mb4.z;
            s.w = f23.y + qk.w + mb4.w;
            sv[i] = s;
            mx = fmaxf(mx, fmaxf(fmaxf(s.x, s.y), fmaxf(s.z, s.w)));
        }
#pragma unroll
        for (int o = 16; o; o >>= 1) mx = fmaxf(mx, __shfl_xor_sync(0xffffffffu, mx, o));

        __half* prow = g_probs + (((size_t)(b * 16 + h)) * 1024 + q) * 1024;
        float sum = 0.f;
#pragma unroll
        for (int i = 0; i < 8; ++i) {
            float e0 = __expf(sv[i].x - mx);
            float e1 = __expf(sv[i].y - mx);
            float e2 = __expf(sv[i].z - mx);
            float e3 = __expf(sv[i].w - mx);
            sum += (e0 + e1) + (e2 + e3);
            __half2 p0 = __floats2half2_rn(e0, e1);
            __half2 p1 = __floats2half2_rn(e2, e3);
            uint2 pk;
            pk.x = reinterpret_cast<unsigned int&>(p0);
            pk.y = reinterpret_cast<unsigned int&>(p1);
            *(uint2*)(prow + lane * 4 + i * 128) = pk;
        }
#pragma unroll
        for (int o = 16; o; o >>= 1) sum += __shfl_xor_sync(0xffffffffu, sum, o);
        if (lane == 0) g_psum[(b * 16 + h) * 1024 + q] = sum;
    }
}

// ---------------- kernel 3: AV + gate ----------------
__global__ __launch_bounds__(256) void av_kernel() {
    __shared__ __half Ps[128][72];
    __shared__ float  Vs[64][36];
    int tid = threadIdx.x;
    int tx = tid & 7;
    int ty = tid >> 3;
    int bh = blockIdx.y;
    int b = bh >> 4, h = bh & 15;
    int q0 = blockIdx.x * 128;

    const __half* pb = g_probs + ((size_t)bh * 1024 + q0) * 1024;
    const float* vb = g_v + (size_t)b * 1024 * 512 + h * 32;

    float acc[4][4] = {};

    for (int kt = 0; kt < 16; ++kt) {
        __syncthreads();
#pragma unroll
        for (int u = 0; u < 4; ++u) {
            int id = tid + 256 * u;
            int row = id >> 3, c8 = id & 7;
            *(uint4*)&Ps[row][c8 * 8] = *(const uint4*)(pb + (size_t)row * 1024 + kt * 64 + c8 * 8);
        }
#pragma unroll
        for (int u = 0; u < 2; ++u) {
            int id = tid + 256 * u;
            int row = id >> 3, d4 = id & 7;
            *(float4*)&Vs[row][d4 * 4] = *(const float4*)(vb + (size_t)(kt * 64 + row) * 512 + d4 * 4);
        }
        __syncthreads();
#pragma unroll 4
        for (int k2 = 0; k2 < 32; ++k2) {
            int kk = k2 * 2;
            float4 v0 = *(const float4*)&Vs[kk][tx * 4];
            float4 v1 = *(const float4*)&Vs[kk + 1][tx * 4];
#pragma unroll
            for (int i = 0; i < 4; ++i) {
                float2 pf = __half22float2(*(const __half2*)&Ps[ty * 4 + i][kk]);
                acc[i][0] += pf.x * v0.x + pf.y * v1.x;
                acc[i][1] += pf.x * v0.y + pf.y * v1.y;
                acc[i][2] += pf.x * v0.z + pf.y * v1.z;
                acc[i][3] += pf.x * v0.w + pf.y * v1.w;
            }
        }
    }

#pragma unroll
    for (int i = 0; i < 4; ++i) {
        int q = q0 + ty * 4 + i;
        float inv = 1.0f / g_psum[bh * 1024 + q];
        size_t gi = ((size_t)(b * 1024 + q)) * 512 + h * 32 + tx * 4;
        float4 gv = *(const float4*)&g_g[gi];
        float4 o;
        o.x = acc[i][0] * inv * gv.x;
        o.y = acc[i][1] * inv * gv.y;
        o.z = acc[i][2] * inv * gv.z;
        o.w = acc[i][3] * inv * gv.w;
        *(float4*)&g_og[gi] = o;
    }
}

// ---------------- kernel 4: out = og @ w_o + b_o ----------------
__global__ __launch_bounds__(256) void out_kernel(const float* __restrict__ wo,
                                                  const float* __restrict__ bo,
                                                  float* __restrict__ out) {
    __shared__ float As[16][68];
    __shared__ float Bs[16][68];
    int bx = blockIdx.x;
    int by = blockIdx.y;
    int tid = threadIdx.x;
    int tx = tid & 15, ty = tid >> 4;
    int cl0 = bx * 64;
    float acc[4][4] = {};
    int aRow = tid >> 2, aK4 = (tid & 3) * 4;
    int bK = tid >> 4, bC4 = (tid & 15) * 4;
    for (int k0 = 0; k0 < 512; k0 += 16) {
        float4 va = *(const float4*)(g_og + (size_t)(by * 64 + aRow) * 512 + k0 + aK4);
        float4 vb = *(const float4*)(wo + (size_t)(k0 + bK) * 512 + cl0 + bC4);
        __syncthreads();
        As[aK4 + 0][aRow] = va.x;
        As[aK4 + 1][aRow] = va.y;
        As[aK4 + 2][aRow] = va.z;
        As[aK4 + 3][aRow] = va.w;
        *(float4*)&Bs[bK][bC4] = vb;
        __syncthreads();
#pragma unroll
        for (int kk = 0; kk < 16; ++kk) {
            float4 a = *(const float4*)&As[kk][ty * 4];
            float4 b = *(const float4*)&Bs[kk][tx * 4];
            float ar[4] = {a.x, a.y, a.z, a.w};
            float br[4] = {b.x, b.y, b.z, b.w};
#pragma unroll
            for (int i = 0; i < 4; ++i)
#pragma unroll
                for (int j = 0; j < 4; ++j) acc[i][j] += ar[i] * br[j];
        }
    }
#pragma unroll
    for (int i = 0; i < 4; ++i) {
        int row = by * 64 + ty * 4 + i;
#pragma unroll
        for (int j = 0; j < 4; ++j) {
            int col = cl0 + tx * 4 + j;
            out[(size_t)row * 512 + col] = acc[i][j] + bo[col];
        }
    }
}

// ---------------- launch ----------------
extern "C" void kernel_launch(void* const* d_in, const int* in_sizes, int n_in,
                              void* d_out, int out_size) {
    const float* m      = (const float*)d_in[0];
    const float* z      = (const float*)d_in[1];
    const float* mask   = (const float*)d_in[2];
    const float* ln_m_w = (const float*)d_in[3];
    const float* ln_m_b = (const float*)d_in[4];
    const float* ln_z_w = (const float*)d_in[5];
    const float* ln_z_b = (const float*)d_in[6];
    const float* w_z    = (const float*)d_in[7];
    const float* w_q    = (const float*)d_in[8];
    const float* w_k    = (const float*)d_in[9];
    const float* w_v    = (const float*)d_in[10];
    const float* w_g    = (const float*)d_in[11];
    const float* b_g    = (const float*)d_in[12];
    const float* w_o    = (const float*)d_in[13];
    const float* b_o    = (const float*)d_in[14];
    float* out = (float*)d_out;

    // floats: 8192 (S16) + 2*6144 (Z) + 1024 (w) + 32 (s1/c0) + 1024 (mbias) = 22560
    const int smem_bias = 22560 * 4;   // 90,240 B -> 2 CTAs/SM
    cudaFuncSetAttribute(bias_attn_kernel,
                         cudaFuncAttributeMaxDynamicSharedMemorySize, smem_bias);

    ln_m_kernel<<<BB * NN, 128>>>(m, ln_m_w, ln_m_b);
    proj_kernel<<<dim3(32, 32), 256>>>(w_q, w_k, w_v, w_g, b_g);
    qk_kernel<<<dim3(64, 32), 512>>>();
    bias_attn_kernel<<<BB * NN, 512, smem_bias>>>(z, mask, ln_z_w, ln_z_b, w_z);
    av_kernel<<<dim3(8, 32), 256>>>();
    out_kernel<<<dim3(8, 32), 256>>>(w_o, b_o, out);
}